// round 1
// baseline (speedup 1.0000x reference)
#include <cuda_runtime.h>
#include <math.h>

// Problem constants
#define BB 2
#define SS 2048
#define DD 1280
#define HH 16
#define DP 80
#define MROWS (BB * SS)          // 4096

// Scratch (device globals: allocation-free rule)
__device__ float g_Q[BB * HH * SS * DP];   // [B,H,S,80]
__device__ float g_K[BB * HH * SS * DP];
__device__ float g_V[BB * HH * SS * DP];
__device__ float g_ctx[BB * SS * DD];      // [B,S,1280] head-merged

// ---------------------------------------------------------------------------
// GEMM: 128x128 tile, BK=8, 256 threads, 8x8 per thread (4+4 split frags)
// ---------------------------------------------------------------------------
#define BM 128
#define BN 128
#define BK 8

// Fused QKV projection: C = x @ [Wq|Wk|Wv] + bias, scattered to [B,H,S,80]
__global__ __launch_bounds__(256) void qkv_gemm_kernel(
    const float* __restrict__ x,
    const float* __restrict__ Wq, const float* __restrict__ Wk, const float* __restrict__ Wv,
    const float* __restrict__ bq, const float* __restrict__ bk, const float* __restrict__ bv)
{
    __shared__ float As[BK][BM];
    __shared__ float Bs[BK][BN];
    const int t  = threadIdx.x;
    const int tx = t & 15;
    const int ty = t >> 4;
    const int bm = blockIdx.y;
    const int bn = blockIdx.x;

    const int ncol0 = bn * BN;            // 0..3839
    const int which = ncol0 / DD;         // 0=Q 1=K 2=V (BN=128 divides 1280)
    const float* W    = (which == 0) ? Wq : (which == 1) ? Wk : Wv;
    const float* bias = (which == 0) ? bq : (which == 1) ? bk : bv;
    float* dst        = (which == 0) ? g_Q : (which == 1) ? g_K : g_V;
    const int nloc0 = ncol0 - which * DD; // column within the 1280-wide matrix

    float acc[8][8];
#pragma unroll
    for (int i = 0; i < 8; i++)
#pragma unroll
        for (int j = 0; j < 8; j++) acc[i][j] = 0.f;

    const int ar = t >> 1;            // 0..127
    const int ac = (t & 1) * 4;       // 0 or 4
    const int br = t >> 5;            // 0..7
    const int bc = (t & 31) * 4;      // 0..124

    const float* Aptr = x + (size_t)(bm * BM + ar) * DD;

    for (int kt = 0; kt < DD; kt += BK) {
        float4 av = *(const float4*)(Aptr + kt + ac);
        As[ac + 0][ar] = av.x; As[ac + 1][ar] = av.y;
        As[ac + 2][ar] = av.z; As[ac + 3][ar] = av.w;
        float4 bv4 = *(const float4*)(W + (size_t)(kt + br) * DD + nloc0 + bc);
        *(float4*)&Bs[br][bc] = bv4;
        __syncthreads();
#pragma unroll
        for (int k = 0; k < BK; k++) {
            float a[8], b[8];
            *(float4*)(a)     = *(const float4*)&As[k][ty * 4];
            *(float4*)(a + 4) = *(const float4*)&As[k][ty * 4 + 64];
            *(float4*)(b)     = *(const float4*)&Bs[k][tx * 4];
            *(float4*)(b + 4) = *(const float4*)&Bs[k][tx * 4 + 64];
#pragma unroll
            for (int i = 0; i < 8; i++)
#pragma unroll
                for (int j = 0; j < 8; j++)
                    acc[i][j] += a[i] * b[j];
        }
        __syncthreads();
    }

    // Epilogue: scatter into [B,H,S,80]
#pragma unroll
    for (int i = 0; i < 8; i++) {
        const int m  = bm * BM + ty * 4 + ((i < 4) ? i : 64 + (i - 4));
        const int b_ = m >> 11;        // /2048
        const int s_ = m & 2047;
#pragma unroll
        for (int j = 0; j < 8; j++) {
            const int col  = nloc0 + tx * 4 + ((j < 4) ? j : 64 + (j - 4));
            const int head = col / DP;
            const int dd   = col - head * DP;
            const float v  = acc[i][j] + bias[col];
            dst[(((size_t)b_ * HH + head) * SS + s_) * DP + dd] = v;
        }
    }
}

// Output projection: out = g_ctx @ Wo + bo (row-major [4096,1280])
__global__ __launch_bounds__(256) void out_gemm_kernel(
    const float* __restrict__ Wo, const float* __restrict__ bo,
    float* __restrict__ out)
{
    __shared__ float As[BK][BM];
    __shared__ float Bs[BK][BN];
    const int t  = threadIdx.x;
    const int tx = t & 15;
    const int ty = t >> 4;
    const int bm = blockIdx.y;
    const int bn = blockIdx.x;
    const int ncol0 = bn * BN;

    float acc[8][8];
#pragma unroll
    for (int i = 0; i < 8; i++)
#pragma unroll
        for (int j = 0; j < 8; j++) acc[i][j] = 0.f;

    const int ar = t >> 1;
    const int ac = (t & 1) * 4;
    const int br = t >> 5;
    const int bc = (t & 31) * 4;

    const float* Aptr = g_ctx + (size_t)(bm * BM + ar) * DD;

    for (int kt = 0; kt < DD; kt += BK) {
        float4 av = *(const float4*)(Aptr + kt + ac);
        As[ac + 0][ar] = av.x; As[ac + 1][ar] = av.y;
        As[ac + 2][ar] = av.z; As[ac + 3][ar] = av.w;
        float4 bv4 = *(const float4*)(Wo + (size_t)(kt + br) * DD + ncol0 + bc);
        *(float4*)&Bs[br][bc] = bv4;
        __syncthreads();
#pragma unroll
        for (int k = 0; k < BK; k++) {
            float a[8], b[8];
            *(float4*)(a)     = *(const float4*)&As[k][ty * 4];
            *(float4*)(a + 4) = *(const float4*)&As[k][ty * 4 + 64];
            *(float4*)(b)     = *(const float4*)&Bs[k][tx * 4];
            *(float4*)(b + 4) = *(const float4*)&Bs[k][tx * 4 + 64];
#pragma unroll
            for (int i = 0; i < 8; i++)
#pragma unroll
                for (int j = 0; j < 8; j++)
                    acc[i][j] += a[i] * b[j];
        }
        __syncthreads();
    }

#pragma unroll
    for (int i = 0; i < 8; i++) {
        const int m = bm * BM + ty * 4 + ((i < 4) ? i : 64 + (i - 4));
#pragma unroll
        for (int j = 0; j < 8; j++) {
            const int col = ncol0 + tx * 4 + ((j < 4) ? j : 64 + (j - 4));
            out[(size_t)m * DD + col] = acc[i][j] + bo[col];
        }
    }
}

// ---------------------------------------------------------------------------
// Flash attention: 64x64 tiles, causal, online softmax. depth = 80.
// Grid (S/64, H, B), 256 threads.
// Smem: Qt[80][68] d-major, Kt[80][68] d-major, Vs[64][84], Ss[64][65]
// ---------------------------------------------------------------------------
#define QT_STR 68
#define VS_STR 84
#define SS_STR 65
#define ATTN_SMEM_FLOATS (80 * QT_STR * 2 + 64 * VS_STR + 64 * SS_STR + 192)

__global__ __launch_bounds__(256) void attn_kernel()
{
    extern __shared__ float sm[];
    float* Qt   = sm;                      // [80][68]
    float* Kt   = Qt + 80 * QT_STR;        // [80][68]
    float* Vs   = Kt + 80 * QT_STR;        // [64][84]
    float* Ss   = Vs + 64 * VS_STR;        // [64][65]
    float* mrow = Ss + 64 * SS_STR;        // [64]
    float* lrow = mrow + 64;               // [64]
    float* corr = lrow + 64;               // [64]

    const int t  = threadIdx.x;
    const int tx = t & 15;
    const int ty = t >> 4;
    const int qt = blockIdx.x;
    const int h  = blockIdx.y;
    const int b  = blockIdx.z;
    const size_t base = ((size_t)b * HH + h) * SS * DP;
    const int qbase = qt * 64;
    const float scale = 0.11180339887498948f;  // 1/sqrt(80)

    // Load Q tile, transposed to d-major
    for (int idx = t; idx < 64 * 20; idx += 256) {
        const int s  = idx / 20;
        const int d4 = (idx % 20) * 4;
        float4 v = *(const float4*)(g_Q + base + (size_t)(qbase + s) * DP + d4);
        Qt[(d4 + 0) * QT_STR + s] = v.x;
        Qt[(d4 + 1) * QT_STR + s] = v.y;
        Qt[(d4 + 2) * QT_STR + s] = v.z;
        Qt[(d4 + 3) * QT_STR + s] = v.w;
    }
    if (t < 64) { mrow[t] = -1e30f; lrow[t] = 0.f; }

    float o[4][5];
#pragma unroll
    for (int i = 0; i < 4; i++)
#pragma unroll
        for (int j = 0; j < 5; j++) o[i][j] = 0.f;

    for (int kt = 0; kt <= qt; kt++) {
        __syncthreads();   // previous PV done before overwriting Kt/Vs
        const int kbase = kt * 64;
        for (int idx = t; idx < 64 * 20; idx += 256) {
            const int s  = idx / 20;
            const int d4 = (idx % 20) * 4;
            float4 kv = *(const float4*)(g_K + base + (size_t)(kbase + s) * DP + d4);
            Kt[(d4 + 0) * QT_STR + s] = kv.x;
            Kt[(d4 + 1) * QT_STR + s] = kv.y;
            Kt[(d4 + 2) * QT_STR + s] = kv.z;
            Kt[(d4 + 3) * QT_STR + s] = kv.w;
            float4 vv = *(const float4*)(g_V + base + (size_t)(kbase + s) * DP + d4);
            *(float4*)&Vs[s * VS_STR + d4] = vv;
        }
        __syncthreads();

        // S = Q @ K^T (4x4 frag per thread)
        float sf[4][4];
#pragma unroll
        for (int i = 0; i < 4; i++)
#pragma unroll
            for (int j = 0; j < 4; j++) sf[i][j] = 0.f;

        for (int d = 0; d < DP; d++) {
            float qv[4], kv[4];
#pragma unroll
            for (int i = 0; i < 4; i++) qv[i] = Qt[d * QT_STR + ty * 4 + i];
#pragma unroll
            for (int j = 0; j < 4; j++) kv[j] = Kt[d * QT_STR + tx * 4 + j];
#pragma unroll
            for (int i = 0; i < 4; i++)
#pragma unroll
                for (int j = 0; j < 4; j++)
                    sf[i][j] += qv[i] * kv[j];
        }

        // scale + causal mask (additive -10000 matching reference) + store
        const bool diag = (kt == qt);
#pragma unroll
        for (int i = 0; i < 4; i++) {
            const int qg = qbase + ty * 4 + i;
#pragma unroll
            for (int j = 0; j < 4; j++) {
                float v = sf[i][j] * scale;
                if (diag && (kbase + tx * 4 + j) > qg) v -= 10000.f;
                Ss[(ty * 4 + i) * SS_STR + tx * 4 + j] = v;
            }
        }
        __syncthreads();

        // online softmax: one thread per row
        if (t < 64) {
            float* row = Ss + t * SS_STR;
            const float mold = mrow[t];
            float mx = mold;
            for (int c = 0; c < 64; c++) mx = fmaxf(mx, row[c]);
            const float cr = __expf(mold - mx);
            float sum = 0.f;
            for (int c = 0; c < 64; c++) {
                const float p = __expf(row[c] - mx);
                row[c] = p;
                sum += p;
            }
            lrow[t] = lrow[t] * cr + sum;
            mrow[t] = mx;
            corr[t] = cr;
        }
        __syncthreads();

        // rescale accumulator, then O += P @ V
        float cr[4];
#pragma unroll
        for (int i = 0; i < 4; i++) cr[i] = corr[ty * 4 + i];
#pragma unroll
        for (int i = 0; i < 4; i++)
#pragma unroll
            for (int j = 0; j < 5; j++) o[i][j] *= cr[i];

        for (int kk = 0; kk < 64; kk++) {
            float p[4], v[5];
#pragma unroll
            for (int i = 0; i < 4; i++) p[i] = Ss[(ty * 4 + i) * SS_STR + kk];
#pragma unroll
            for (int j = 0; j < 5; j++) v[j] = Vs[kk * VS_STR + tx * 5 + j];
#pragma unroll
            for (int i = 0; i < 4; i++)
#pragma unroll
                for (int j = 0; j < 5; j++)
                    o[i][j] += p[i] * v[j];
        }
    }

    // normalize and write ctx [B,S,H*80]
#pragma unroll
    for (int i = 0; i < 4; i++) {
        const int r = ty * 4 + i;
        const float inv_l = 1.f / lrow[r];
#pragma unroll
        for (int j = 0; j < 5; j++) {
            g_ctx[((size_t)b * SS + qbase + r) * DD + h * DP + tx * 5 + j] =
                o[i][j] * inv_l;
        }
    }
}

// ---------------------------------------------------------------------------
extern "C" void kernel_launch(void* const* d_in, const int* in_sizes, int n_in,
                              void* d_out, int out_size)
{
    const float* x  = (const float*)d_in[0];
    // d_in[1] = mask (unused; causal structure implemented directly)
    const float* Wq = (const float*)d_in[2];
    const float* bq = (const float*)d_in[3];
    const float* Wk = (const float*)d_in[4];
    const float* bk = (const float*)d_in[5];
    const float* Wv = (const float*)d_in[6];
    const float* bv = (const float*)d_in[7];
    const float* Wo = (const float*)d_in[8];
    const float* bo = (const float*)d_in[9];
    float* out = (float*)d_out;

    qkv_gemm_kernel<<<dim3(3 * DD / BN, MROWS / BM), 256>>>(x, Wq, Wk, Wv, bq, bk, bv);

    const int smem_bytes = ATTN_SMEM_FLOATS * (int)sizeof(float);
    cudaFuncSetAttribute(attn_kernel, cudaFuncAttributeMaxDynamicSharedMemorySize, smem_bytes);
    attn_kernel<<<dim3(SS / 64, HH, BB), 256, smem_bytes>>>();

    out_gemm_kernel<<<dim3(DD / BN, MROWS / BM), 256>>>(Wo, bo, out);
}

// round 3
// speedup vs baseline: 1.1998x; 1.1998x over previous
#include <cuda_runtime.h>
#include <cuda_bf16.h>
#include <cstdint>
#include <math.h>

// Problem constants
#define BB 2
#define SS 2048
#define DD 1280
#define HH 16
#define DP 80
#define MROWS (BB * SS)          // 4096
#define NQKV (3 * DD)            // 3840

// ---------------------------------------------------------------------------
// Device scratch (allocation-free rule)
// ---------------------------------------------------------------------------
__device__ float g_Q[BB * HH * SS * DP];   // [B,H,S,80]
__device__ float g_K[BB * HH * SS * DP];
__device__ float g_V[BB * HH * SS * DP];
__device__ float g_ctx[BB * SS * DD];      // [B,S,1280]

__device__ __nv_bfloat16 g_Xhi[MROWS * DD];
__device__ __nv_bfloat16 g_Xlo[MROWS * DD];
__device__ __nv_bfloat16 g_WThi[4 * DD * DD];   // rows [0,3840)=Wq,Wk,Wv^T ; [3840,5120)=Wo^T
__device__ __nv_bfloat16 g_WTlo[4 * DD * DD];
__device__ __nv_bfloat16 g_Chi[MROWS * DD];
__device__ __nv_bfloat16 g_Clo[MROWS * DD];

// ---------------------------------------------------------------------------
// mma.sync helper (bf16 x bf16 -> fp32, m16n8k16) — portable to sm_103
// ---------------------------------------------------------------------------
__device__ __forceinline__ void mma16816(float* c, const uint32_t* a, const uint32_t* b) {
    asm volatile(
        "mma.sync.aligned.m16n8k16.row.col.f32.bf16.bf16.f32 "
        "{%0,%1,%2,%3}, {%4,%5,%6,%7}, {%8,%9}, {%0,%1,%2,%3};"
        : "+f"(c[0]), "+f"(c[1]), "+f"(c[2]), "+f"(c[3])
        : "r"(a[0]), "r"(a[1]), "r"(a[2]), "r"(a[3]), "r"(b[0]), "r"(b[1]));
}

// ---------------------------------------------------------------------------
// fp32 -> (bf16 hi, bf16 lo) elementwise split
// ---------------------------------------------------------------------------
__global__ __launch_bounds__(256) void split_kernel(const float* __restrict__ src,
                                                    __nv_bfloat16* __restrict__ hi,
                                                    __nv_bfloat16* __restrict__ lo,
                                                    int n2) {
    int i = blockIdx.x * blockDim.x + threadIdx.x;
    if (i >= n2) return;
    float2 v = *(const float2*)(src + 2 * (size_t)i);
    __nv_bfloat16 h0 = __float2bfloat16(v.x);
    __nv_bfloat16 h1 = __float2bfloat16(v.y);
    __nv_bfloat16 l0 = __float2bfloat16(v.x - __bfloat162float(h0));
    __nv_bfloat16 l1 = __float2bfloat16(v.y - __bfloat162float(h1));
    *(__nv_bfloat162*)(hi + 2 * (size_t)i) = __nv_bfloat162(h0, h1);
    *(__nv_bfloat162*)(lo + 2 * (size_t)i) = __nv_bfloat162(l0, l1);
}

// ---------------------------------------------------------------------------
// W [K=1280, N=1280] row-major -> W^T split into g_WThi/lo rows [ro, ro+1280)
// ---------------------------------------------------------------------------
__global__ __launch_bounds__(256) void wsplit_kernel(const float* __restrict__ W, int ro) {
    __shared__ float tile[32][33];
    const int tx = threadIdx.x;        // 0..31
    const int ty = threadIdx.y;        // 0..7
    const int n0 = blockIdx.x * 32;
    const int k0 = blockIdx.y * 32;
#pragma unroll
    for (int q = 0; q < 4; q++)
        tile[ty + q * 8][tx] = W[(size_t)(k0 + ty + q * 8) * DD + n0 + tx];
    __syncthreads();
#pragma unroll
    for (int q = 0; q < 4; q++) {
        const int nn = n0 + ty + q * 8;
        const int kk = k0 + tx;
        float v = tile[tx][ty + q * 8];
        __nv_bfloat16 h = __float2bfloat16(v);
        __nv_bfloat16 l = __float2bfloat16(v - __bfloat162float(h));
        g_WThi[(size_t)(ro + nn) * DD + kk] = h;
        g_WTlo[(size_t)(ro + nn) * DD + kk] = l;
    }
}

// ---------------------------------------------------------------------------
// HMMA split-bf16 GEMM: C[128x128 tile] = A @ B^T (+bias)
// A: [M x 1280] bf16 hi/lo row-major; B: [N x 1280] bf16 hi/lo row-major.
// 8 warps (2x4), warp tile 64x32, mma.m16n8k16, 3 products.
// mode 0: scatter into g_Q/g_K/g_V per QKV column space (N=3840)
// mode 1: plain write to outp [M x 1280] + bias b0
// ---------------------------------------------------------------------------
#define BK2 32
#define AP 40      // smem pitch in bf16 (40*2B = 80B -> conflict-free)

__global__ __launch_bounds__(256, 2) void mma_gemm_kernel(
    const __nv_bfloat16* __restrict__ Ahi, const __nv_bfloat16* __restrict__ Alo,
    const __nv_bfloat16* __restrict__ Bhi, const __nv_bfloat16* __restrict__ Blo,
    const float* __restrict__ b0, const float* __restrict__ b1, const float* __restrict__ b2,
    int mode, float* __restrict__ outp)
{
    __shared__ __nv_bfloat16 sAhi[128 * AP];
    __shared__ __nv_bfloat16 sAlo[128 * AP];
    __shared__ __nv_bfloat16 sBhi[128 * AP];
    __shared__ __nv_bfloat16 sBlo[128 * AP];

    const int t    = threadIdx.x;
    const int wid  = t >> 5;
    const int lane = t & 31;
    const int n0   = blockIdx.x * 128;
    const int m0   = blockIdx.y * 128;
    const int wm   = (wid >> 2) * 64;     // warp row offset
    const int wn   = (wid & 3) * 32;      // warp col offset
    const int g    = lane >> 2;           // 0..7
    const int t4   = lane & 3;            // 0..3

    const int lr = t >> 1;                // load row 0..127
    const int lc = (t & 1) * 16;          // load col base

    float acc[4][4][4];
#pragma unroll
    for (int mi = 0; mi < 4; mi++)
#pragma unroll
        for (int ni = 0; ni < 4; ni++)
#pragma unroll
            for (int q = 0; q < 4; q++) acc[mi][ni][q] = 0.f;

    for (int kc = 0; kc < DD / BK2; kc++) {
        const int kk = kc * BK2;
        const __nv_bfloat16* pAhi = Ahi + (size_t)(m0 + lr) * DD + kk + lc;
        const __nv_bfloat16* pAlo = Alo + (size_t)(m0 + lr) * DD + kk + lc;
        const __nv_bfloat16* pBhi = Bhi + (size_t)(n0 + lr) * DD + kk + lc;
        const __nv_bfloat16* pBlo = Blo + (size_t)(n0 + lr) * DD + kk + lc;
#pragma unroll
        for (int u = 0; u < 4; u++) {
            const int so = lr * AP + lc + u * 4;
            *(uint2*)&sAhi[so] = *(const uint2*)(pAhi + u * 4);
            *(uint2*)&sAlo[so] = *(const uint2*)(pAlo + u * 4);
            *(uint2*)&sBhi[so] = *(const uint2*)(pBhi + u * 4);
            *(uint2*)&sBlo[so] = *(const uint2*)(pBlo + u * 4);
        }
        __syncthreads();

#pragma unroll
        for (int ks = 0; ks < 2; ks++) {
            const int kb = ks * 16;
            // B fragments (4 n-frags, hi+lo)
            uint32_t bh[4][2], bl[4][2];
#pragma unroll
            for (int ni = 0; ni < 4; ni++) {
                const int col = wn + ni * 8 + g;        // n index (row of Bsm)
                const int koff = kb + t4 * 2;
                bh[ni][0] = *(const uint32_t*)&sBhi[col * AP + koff];
                bh[ni][1] = *(const uint32_t*)&sBhi[col * AP + koff + 8];
                bl[ni][0] = *(const uint32_t*)&sBlo[col * AP + koff];
                bl[ni][1] = *(const uint32_t*)&sBlo[col * AP + koff + 8];
            }
#pragma unroll
            for (int mi = 0; mi < 4; mi++) {
                const int row = wm + mi * 16 + g;
                const int koff = kb + t4 * 2;
                uint32_t ah[4], al[4];
                ah[0] = *(const uint32_t*)&sAhi[row * AP + koff];
                ah[1] = *(const uint32_t*)&sAhi[(row + 8) * AP + koff];
                ah[2] = *(const uint32_t*)&sAhi[row * AP + koff + 8];
                ah[3] = *(const uint32_t*)&sAhi[(row + 8) * AP + koff + 8];
                al[0] = *(const uint32_t*)&sAlo[row * AP + koff];
                al[1] = *(const uint32_t*)&sAlo[(row + 8) * AP + koff];
                al[2] = *(const uint32_t*)&sAlo[row * AP + koff + 8];
                al[3] = *(const uint32_t*)&sAlo[(row + 8) * AP + koff + 8];
#pragma unroll
                for (int ni = 0; ni < 4; ni++) {
                    mma16816(acc[mi][ni], ah, bh[ni]);
                    mma16816(acc[mi][ni], ah, bl[ni]);
                    mma16816(acc[mi][ni], al, bh[ni]);
                }
            }
        }
        __syncthreads();
    }

    // Epilogue
#pragma unroll
    for (int mi = 0; mi < 4; mi++) {
        const int r0 = m0 + wm + mi * 16 + g;
#pragma unroll
        for (int ni = 0; ni < 4; ni++) {
            const int cg0 = n0 + wn + ni * 8 + t4 * 2;
#pragma unroll
            for (int q = 0; q < 4; q++) {
                const int row = r0 + (q >> 1) * 8;      // q=0,1 -> r0 ; q=2,3 -> r0+8
                const int cg  = cg0 + (q & 1);
                const float v = acc[mi][ni][q];
                if (mode == 0) {
                    const int which = cg / DD;
                    const int cl    = cg - which * DD;
                    const int head  = cl / DP;
                    const int dd    = cl - head * DP;
                    const float bias = (which == 0 ? b0 : which == 1 ? b1 : b2)[cl];
                    float* dst = (which == 0) ? g_Q : (which == 1) ? g_K : g_V;
                    const int b_ = row >> 11;
                    const int s_ = row & 2047;
                    dst[(((size_t)b_ * HH + head) * SS + s_) * DP + dd] = v + bias;
                } else {
                    outp[(size_t)row * DD + cg] = v + b0[cg];
                }
            }
        }
    }
}

// ---------------------------------------------------------------------------
// Flash attention (fp32 SIMT, unchanged from R1)
// ---------------------------------------------------------------------------
#define QT_STR 68
#define VS_STR 84
#define SS_STR 65
#define ATTN_SMEM_FLOATS (80 * QT_STR * 2 + 64 * VS_STR + 64 * SS_STR + 192)

__global__ __launch_bounds__(256) void attn_kernel()
{
    extern __shared__ float sm[];
    float* Qt   = sm;
    float* Kt   = Qt + 80 * QT_STR;
    float* Vs   = Kt + 80 * QT_STR;
    float* Ss   = Vs + 64 * VS_STR;
    float* mrow = Ss + 64 * SS_STR;
    float* lrow = mrow + 64;
    float* corr = lrow + 64;

    const int t  = threadIdx.x;
    const int tx = t & 15;
    const int ty = t >> 4;
    const int qt = blockIdx.x;
    const int h  = blockIdx.y;
    const int b  = blockIdx.z;
    const size_t base = ((size_t)b * HH + h) * SS * DP;
    const int qbase = qt * 64;
    const float scale = 0.11180339887498948f;

    for (int idx = t; idx < 64 * 20; idx += 256) {
        const int s  = idx / 20;
        const int d4 = (idx % 20) * 4;
        float4 v = *(const float4*)(g_Q + base + (size_t)(qbase + s) * DP + d4);
        Qt[(d4 + 0) * QT_STR + s] = v.x;
        Qt[(d4 + 1) * QT_STR + s] = v.y;
        Qt[(d4 + 2) * QT_STR + s] = v.z;
        Qt[(d4 + 3) * QT_STR + s] = v.w;
    }
    if (t < 64) { mrow[t] = -1e30f; lrow[t] = 0.f; }

    float o[4][5];
#pragma unroll
    for (int i = 0; i < 4; i++)
#pragma unroll
        for (int j = 0; j < 5; j++) o[i][j] = 0.f;

    for (int kt = 0; kt <= qt; kt++) {
        __syncthreads();
        const int kbase = kt * 64;
        for (int idx = t; idx < 64 * 20; idx += 256) {
            const int s  = idx / 20;
            const int d4 = (idx % 20) * 4;
            float4 kv = *(const float4*)(g_K + base + (size_t)(kbase + s) * DP + d4);
            Kt[(d4 + 0) * QT_STR + s] = kv.x;
            Kt[(d4 + 1) * QT_STR + s] = kv.y;
            Kt[(d4 + 2) * QT_STR + s] = kv.z;
            Kt[(d4 + 3) * QT_STR + s] = kv.w;
            float4 vv = *(const float4*)(g_V + base + (size_t)(kbase + s) * DP + d4);
            *(float4*)&Vs[s * VS_STR + d4] = vv;
        }
        __syncthreads();

        float sf[4][4];
#pragma unroll
        for (int i = 0; i < 4; i++)
#pragma unroll
            for (int j = 0; j < 4; j++) sf[i][j] = 0.f;

        for (int d = 0; d < DP; d++) {
            float qv[4], kv[4];
#pragma unroll
            for (int i = 0; i < 4; i++) qv[i] = Qt[d * QT_STR + ty * 4 + i];
#pragma unroll
            for (int j = 0; j < 4; j++) kv[j] = Kt[d * QT_STR + tx * 4 + j];
#pragma unroll
            for (int i = 0; i < 4; i++)
#pragma unroll
                for (int j = 0; j < 4; j++)
                    sf[i][j] += qv[i] * kv[j];
        }

        const bool diag = (kt == qt);
#pragma unroll
        for (int i = 0; i < 4; i++) {
            const int qg = qbase + ty * 4 + i;
#pragma unroll
            for (int j = 0; j < 4; j++) {
                float v = sf[i][j] * scale;
                if (diag && (kbase + tx * 4 + j) > qg) v -= 10000.f;
                Ss[(ty * 4 + i) * SS_STR + tx * 4 + j] = v;
            }
        }
        __syncthreads();

        if (t < 64) {
            float* row = Ss + t * SS_STR;
            const float mold = mrow[t];
            float mx = mold;
            for (int c = 0; c < 64; c++) mx = fmaxf(mx, row[c]);
            const float cr = __expf(mold - mx);
            float sum = 0.f;
            for (int c = 0; c < 64; c++) {
                const float p = __expf(row[c] - mx);
                row[c] = p;
                sum += p;
            }
            lrow[t] = lrow[t] * cr + sum;
            mrow[t] = mx;
            corr[t] = cr;
        }
        __syncthreads();

        float cr[4];
#pragma unroll
        for (int i = 0; i < 4; i++) cr[i] = corr[ty * 4 + i];
#pragma unroll
        for (int i = 0; i < 4; i++)
#pragma unroll
            for (int j = 0; j < 5; j++) o[i][j] *= cr[i];

        for (int kk = 0; kk < 64; kk++) {
            float p[4], v[5];
#pragma unroll
            for (int i = 0; i < 4; i++) p[i] = Ss[(ty * 4 + i) * SS_STR + kk];
#pragma unroll
            for (int j = 0; j < 5; j++) v[j] = Vs[kk * VS_STR + tx * 5 + j];
#pragma unroll
            for (int i = 0; i < 4; i++)
#pragma unroll
                for (int j = 0; j < 5; j++)
                    o[i][j] += p[i] * v[j];
        }
    }

#pragma unroll
    for (int i = 0; i < 4; i++) {
        const int rr = ty * 4 + i;
        const float inv_l = 1.f / lrow[rr];
#pragma unroll
        for (int j = 0; j < 5; j++) {
            g_ctx[((size_t)b * SS + qbase + rr) * DD + h * DP + tx * 5 + j] =
                o[i][j] * inv_l;
        }
    }
}

// ---------------------------------------------------------------------------
extern "C" void kernel_launch(void* const* d_in, const int* in_sizes, int n_in,
                              void* d_out, int out_size)
{
    const float* x  = (const float*)d_in[0];
    const float* Wq = (const float*)d_in[2];
    const float* bq = (const float*)d_in[3];
    const float* Wk = (const float*)d_in[4];
    const float* bk = (const float*)d_in[5];
    const float* Wv = (const float*)d_in[6];
    const float* bv = (const float*)d_in[7];
    const float* Wo = (const float*)d_in[8];
    const float* bo = (const float*)d_in[9];
    float* out = (float*)d_out;

    __nv_bfloat16 *xhi, *xlo, *wthi, *wtlo, *chi, *clo;
    cudaGetSymbolAddress((void**)&xhi, g_Xhi);
    cudaGetSymbolAddress((void**)&xlo, g_Xlo);
    cudaGetSymbolAddress((void**)&wthi, g_WThi);
    cudaGetSymbolAddress((void**)&wtlo, g_WTlo);
    cudaGetSymbolAddress((void**)&chi, g_Chi);
    cudaGetSymbolAddress((void**)&clo, g_Clo);
    float* ctxp;
    cudaGetSymbolAddress((void**)&ctxp, g_ctx);

    // 1. split x
    {
        const int n2 = MROWS * DD / 2;
        split_kernel<<<(n2 + 255) / 256, 256>>>(x, xhi, xlo, n2);
    }
    // 2. transpose+split weights
    wsplit_kernel<<<dim3(40, 40), dim3(32, 8)>>>(Wq, 0);
    wsplit_kernel<<<dim3(40, 40), dim3(32, 8)>>>(Wk, DD);
    wsplit_kernel<<<dim3(40, 40), dim3(32, 8)>>>(Wv, 2 * DD);
    wsplit_kernel<<<dim3(40, 40), dim3(32, 8)>>>(Wo, 3 * DD);

    // 3. QKV projection (HMMA)
    mma_gemm_kernel<<<dim3(NQKV / 128, MROWS / 128), 256>>>(
        xhi, xlo, wthi, wtlo, bq, bk, bv, 0, nullptr);

    // 4. attention
    const int attn_smem = ATTN_SMEM_FLOATS * (int)sizeof(float);
    cudaFuncSetAttribute(attn_kernel, cudaFuncAttributeMaxDynamicSharedMemorySize, attn_smem);
    attn_kernel<<<dim3(SS / 64, HH, BB), 256, attn_smem>>>();

    // 5. split ctx
    {
        const int n2 = MROWS * DD / 2;
        split_kernel<<<(n2 + 255) / 256, 256>>>(ctxp, chi, clo, n2);
    }

    // 6. output projection (HMMA)
    mma_gemm_kernel<<<dim3(DD / 128, MROWS / 128), 256>>>(
        chi, clo, wthi + (size_t)3 * DD * DD, wtlo + (size_t)3 * DD * DD,
        bo, nullptr, nullptr, 1, out);
}

// round 4
// speedup vs baseline: 1.6104x; 1.3422x over previous
#include <cuda_runtime.h>
#include <cuda_bf16.h>
#include <cstdint>
#include <math.h>

// Problem constants
#define BB 2
#define SS 2048
#define DD 1280
#define HH 16
#define DP 80
#define MROWS (BB * SS)          // 4096
#define NQKV (3 * DD)            // 3840

// ---------------------------------------------------------------------------
// Device scratch (allocation-free rule)
// ---------------------------------------------------------------------------
__device__ __nv_bfloat16 g_Qhi[BB * HH * SS * DP];
__device__ __nv_bfloat16 g_Qlo[BB * HH * SS * DP];
__device__ __nv_bfloat16 g_Khi[BB * HH * SS * DP];
__device__ __nv_bfloat16 g_Klo[BB * HH * SS * DP];
__device__ __nv_bfloat16 g_Vhi[BB * HH * SS * DP];
__device__ __nv_bfloat16 g_Vlo[BB * HH * SS * DP];

__device__ __nv_bfloat16 g_Xhi[MROWS * DD];
__device__ __nv_bfloat16 g_Xlo[MROWS * DD];
__device__ __nv_bfloat16 g_WThi[4 * DD * DD];   // rows [0,3840)=Wq,Wk,Wv^T ; [3840,5120)=Wo^T
__device__ __nv_bfloat16 g_WTlo[4 * DD * DD];
__device__ __nv_bfloat16 g_Chi[MROWS * DD];
__device__ __nv_bfloat16 g_Clo[MROWS * DD];

// ---------------------------------------------------------------------------
// mma.sync helper (bf16 x bf16 -> fp32, m16n8k16) — portable to sm_103
// ---------------------------------------------------------------------------
__device__ __forceinline__ void mma16816(float* c, const uint32_t* a, const uint32_t* b) {
    asm volatile(
        "mma.sync.aligned.m16n8k16.row.col.f32.bf16.bf16.f32 "
        "{%0,%1,%2,%3}, {%4,%5,%6,%7}, {%8,%9}, {%0,%1,%2,%3};"
        : "+f"(c[0]), "+f"(c[1]), "+f"(c[2]), "+f"(c[3])
        : "r"(a[0]), "r"(a[1]), "r"(a[2]), "r"(a[3]), "r"(b[0]), "r"(b[1]));
}

// split a,b -> packed bf16x2 hi and lo (a in lower half, b in upper half)
__device__ __forceinline__ void split_pack2(float a, float b, uint32_t& hi, uint32_t& lo) {
    __nv_bfloat16 ha = __float2bfloat16(a), hb = __float2bfloat16(b);
    __nv_bfloat16 la = __float2bfloat16(a - __bfloat162float(ha));
    __nv_bfloat16 lb = __float2bfloat16(b - __bfloat162float(hb));
    __nv_bfloat162 H = __nv_bfloat162(ha, hb);
    __nv_bfloat162 L = __nv_bfloat162(la, lb);
    hi = *(uint32_t*)&H;
    lo = *(uint32_t*)&L;
}

// ---------------------------------------------------------------------------
// fp32 -> (bf16 hi, bf16 lo) elementwise split
// ---------------------------------------------------------------------------
__global__ __launch_bounds__(256) void split_kernel(const float* __restrict__ src,
                                                    __nv_bfloat16* __restrict__ hi,
                                                    __nv_bfloat16* __restrict__ lo,
                                                    int n2) {
    int i = blockIdx.x * blockDim.x + threadIdx.x;
    if (i >= n2) return;
    float2 v = *(const float2*)(src + 2 * (size_t)i);
    __nv_bfloat16 h0 = __float2bfloat16(v.x);
    __nv_bfloat16 h1 = __float2bfloat16(v.y);
    __nv_bfloat16 l0 = __float2bfloat16(v.x - __bfloat162float(h0));
    __nv_bfloat16 l1 = __float2bfloat16(v.y - __bfloat162float(h1));
    *(__nv_bfloat162*)(hi + 2 * (size_t)i) = __nv_bfloat162(h0, h1);
    *(__nv_bfloat162*)(lo + 2 * (size_t)i) = __nv_bfloat162(l0, l1);
}

// ---------------------------------------------------------------------------
// W [K=1280, N=1280] row-major -> W^T split into g_WThi/lo rows [ro, ro+1280)
// ---------------------------------------------------------------------------
__global__ __launch_bounds__(256) void wsplit_kernel(const float* __restrict__ W, int ro) {
    __shared__ float tile[32][33];
    const int tx = threadIdx.x;
    const int ty = threadIdx.y;
    const int n0 = blockIdx.x * 32;
    const int k0 = blockIdx.y * 32;
#pragma unroll
    for (int q = 0; q < 4; q++)
        tile[ty + q * 8][tx] = W[(size_t)(k0 + ty + q * 8) * DD + n0 + tx];
    __syncthreads();
#pragma unroll
    for (int q = 0; q < 4; q++) {
        const int nn = n0 + ty + q * 8;
        const int kk = k0 + tx;
        float v = tile[tx][ty + q * 8];
        __nv_bfloat16 h = __float2bfloat16(v);
        __nv_bfloat16 l = __float2bfloat16(v - __bfloat162float(h));
        g_WThi[(size_t)(ro + nn) * DD + kk] = h;
        g_WTlo[(size_t)(ro + nn) * DD + kk] = l;
    }
}

// ---------------------------------------------------------------------------
// HMMA split-bf16 GEMM: C[128x128 tile] = A @ B^T (+bias)
// mode 0: scatter into g_Q/K/V hi+lo split arrays (QKV column space, N=3840)
// mode 1: plain fp32 write to outp [M x 1280] + bias b0
// ---------------------------------------------------------------------------
#define BK2 32
#define AP 40      // smem pitch in bf16

__global__ __launch_bounds__(256, 2) void mma_gemm_kernel(
    const __nv_bfloat16* __restrict__ Ahi, const __nv_bfloat16* __restrict__ Alo,
    const __nv_bfloat16* __restrict__ Bhi, const __nv_bfloat16* __restrict__ Blo,
    const float* __restrict__ b0, const float* __restrict__ b1, const float* __restrict__ b2,
    int mode, float* __restrict__ outp)
{
    __shared__ __nv_bfloat16 sAhi[128 * AP];
    __shared__ __nv_bfloat16 sAlo[128 * AP];
    __shared__ __nv_bfloat16 sBhi[128 * AP];
    __shared__ __nv_bfloat16 sBlo[128 * AP];

    const int t    = threadIdx.x;
    const int wid  = t >> 5;
    const int lane = t & 31;
    const int n0   = blockIdx.x * 128;
    const int m0   = blockIdx.y * 128;
    const int wm   = (wid >> 2) * 64;
    const int wn   = (wid & 3) * 32;
    const int g    = lane >> 2;
    const int t4   = lane & 3;

    const int lr = t >> 1;
    const int lc = (t & 1) * 16;

    float acc[4][4][4];
#pragma unroll
    for (int mi = 0; mi < 4; mi++)
#pragma unroll
        for (int ni = 0; ni < 4; ni++)
#pragma unroll
            for (int q = 0; q < 4; q++) acc[mi][ni][q] = 0.f;

    for (int kc = 0; kc < DD / BK2; kc++) {
        const int kk = kc * BK2;
        const __nv_bfloat16* pAhi = Ahi + (size_t)(m0 + lr) * DD + kk + lc;
        const __nv_bfloat16* pAlo = Alo + (size_t)(m0 + lr) * DD + kk + lc;
        const __nv_bfloat16* pBhi = Bhi + (size_t)(n0 + lr) * DD + kk + lc;
        const __nv_bfloat16* pBlo = Blo + (size_t)(n0 + lr) * DD + kk + lc;
#pragma unroll
        for (int u = 0; u < 4; u++) {
            const int so = lr * AP + lc + u * 4;
            *(uint2*)&sAhi[so] = *(const uint2*)(pAhi + u * 4);
            *(uint2*)&sAlo[so] = *(const uint2*)(pAlo + u * 4);
            *(uint2*)&sBhi[so] = *(const uint2*)(pBhi + u * 4);
            *(uint2*)&sBlo[so] = *(const uint2*)(pBlo + u * 4);
        }
        __syncthreads();

#pragma unroll
        for (int ks = 0; ks < 2; ks++) {
            const int kb = ks * 16;
            uint32_t bh[4][2], bl[4][2];
#pragma unroll
            for (int ni = 0; ni < 4; ni++) {
                const int col = wn + ni * 8 + g;
                const int koff = kb + t4 * 2;
                bh[ni][0] = *(const uint32_t*)&sBhi[col * AP + koff];
                bh[ni][1] = *(const uint32_t*)&sBhi[col * AP + koff + 8];
                bl[ni][0] = *(const uint32_t*)&sBlo[col * AP + koff];
                bl[ni][1] = *(const uint32_t*)&sBlo[col * AP + koff + 8];
            }
#pragma unroll
            for (int mi = 0; mi < 4; mi++) {
                const int row = wm + mi * 16 + g;
                const int koff = kb + t4 * 2;
                uint32_t ah[4], al[4];
                ah[0] = *(const uint32_t*)&sAhi[row * AP + koff];
                ah[1] = *(const uint32_t*)&sAhi[(row + 8) * AP + koff];
                ah[2] = *(const uint32_t*)&sAhi[row * AP + koff + 8];
                ah[3] = *(const uint32_t*)&sAhi[(row + 8) * AP + koff + 8];
                al[0] = *(const uint32_t*)&sAlo[row * AP + koff];
                al[1] = *(const uint32_t*)&sAlo[(row + 8) * AP + koff];
                al[2] = *(const uint32_t*)&sAlo[row * AP + koff + 8];
                al[3] = *(const uint32_t*)&sAlo[(row + 8) * AP + koff + 8];
#pragma unroll
                for (int ni = 0; ni < 4; ni++) {
                    mma16816(acc[mi][ni], ah, bh[ni]);
                    mma16816(acc[mi][ni], ah, bl[ni]);
                    mma16816(acc[mi][ni], al, bh[ni]);
                }
            }
        }
        __syncthreads();
    }

    // Epilogue
#pragma unroll
    for (int mi = 0; mi < 4; mi++) {
        const int r0 = m0 + wm + mi * 16 + g;
#pragma unroll
        for (int ni = 0; ni < 4; ni++) {
            const int cg0 = n0 + wn + ni * 8 + t4 * 2;
#pragma unroll
            for (int q = 0; q < 4; q++) {
                const int row = r0 + (q >> 1) * 8;
                const int cg  = cg0 + (q & 1);
                const float v = acc[mi][ni][q];
                if (mode == 0) {
                    const int which = cg / DD;
                    const int cl    = cg - which * DD;
                    const int head  = cl / DP;
                    const int dd    = cl - head * DP;
                    const float val = v + (which == 0 ? b0 : which == 1 ? b1 : b2)[cl];
                    __nv_bfloat16* dh = (which == 0) ? g_Qhi : (which == 1) ? g_Khi : g_Vhi;
                    __nv_bfloat16* dl = (which == 0) ? g_Qlo : (which == 1) ? g_Klo : g_Vlo;
                    const int b_ = row >> 11;
                    const int s_ = row & 2047;
                    const size_t idx = (((size_t)b_ * HH + head) * SS + s_) * DP + dd;
                    __nv_bfloat16 hv = __float2bfloat16(val);
                    dh[idx] = hv;
                    dl[idx] = __float2bfloat16(val - __bfloat162float(hv));
                } else {
                    outp[(size_t)row * DD + cg] = v + b0[cg];
                }
            }
        }
    }
}

// ---------------------------------------------------------------------------
// HMMA flash attention: 128 q-rows x 64-key tiles, 8 warps x 16 rows.
// Split bf16 x3 for both QK^T and PV. Writes ctx as bf16 hi/lo split.
// ---------------------------------------------------------------------------
#define QP 84     // Q/K smem pitch (bf16)
#define VP 72     // Vt smem pitch (bf16)
#define ATT_SMEM_BF16 (2 * 128 * QP + 2 * 64 * QP + 2 * 80 * VP)

__global__ __launch_bounds__(256, 2) void attn_mma_kernel()
{
    extern __shared__ __nv_bfloat16 sm[];
    __nv_bfloat16* sQh = sm;
    __nv_bfloat16* sQl = sQh + 128 * QP;
    __nv_bfloat16* sKh = sQl + 128 * QP;
    __nv_bfloat16* sKl = sKh + 64 * QP;
    __nv_bfloat16* sVh = sKl + 64 * QP;   // transposed [80][VP]
    __nv_bfloat16* sVl = sVh + 80 * VP;

    const int t    = threadIdx.x;
    const int wid  = t >> 5;
    const int lane = t & 31;
    const int g    = lane >> 2;
    const int t4   = lane & 3;
    const int qt   = (int)(gridDim.x - 1) - (int)blockIdx.x;   // big tiles first
    const int h    = blockIdx.y;
    const int b    = blockIdx.z;
    const size_t bh = ((size_t)b * HH + h) * SS * DP;
    const int qbase = qt * 128;
    const int wm    = wid * 16;
    const float scale = 0.11180339887498948f;   // 1/sqrt(80)

    // Load Q tile (128 x 80), hi+lo
    {
        const uint32_t* gh = (const uint32_t*)g_Qhi + (bh + (size_t)qbase * DP) / 2;
        const uint32_t* gl = (const uint32_t*)g_Qlo + (bh + (size_t)qbase * DP) / 2;
        for (int i = t; i < 128 * 40; i += 256) {
            const int row = i / 40, cp = i % 40;
            *(uint32_t*)&sQh[row * QP + cp * 2] = gh[row * 40 + cp];
            *(uint32_t*)&sQl[row * QP + cp * 2] = gl[row * 40 + cp];
        }
    }

    float oacc[10][4];
#pragma unroll
    for (int nj = 0; nj < 10; nj++)
#pragma unroll
        for (int q = 0; q < 4; q++) oacc[nj][q] = 0.f;
    float m0 = -1e30f, m1 = -1e30f, l0 = 0.f, l1 = 0.f;

    const int gr0 = qbase + wm + g;
    const int gr1 = gr0 + 8;
    const int ktiles = 2 * qt + 2;

    for (int kb = 0; kb < ktiles; kb++) {
        __syncthreads();
        // Load K (64x80) and V transposed (80x64), hi+lo
        {
            const size_t koff = (bh + (size_t)kb * 64 * DP) / 2;
            const uint32_t* kh = (const uint32_t*)g_Khi + koff;
            const uint32_t* kl = (const uint32_t*)g_Klo + koff;
            const uint32_t* vh = (const uint32_t*)g_Vhi + koff;
            const uint32_t* vl = (const uint32_t*)g_Vlo + koff;
            for (int i = t; i < 64 * 40; i += 256) {
                const int row = i / 40, cp = i % 40;
                *(uint32_t*)&sKh[row * QP + cp * 2] = kh[row * 40 + cp];
                *(uint32_t*)&sKl[row * QP + cp * 2] = kl[row * 40 + cp];
                uint32_t wvh = vh[row * 40 + cp], wvl = vl[row * 40 + cp];
                __nv_bfloat162 Hh = *(__nv_bfloat162*)&wvh;
                __nv_bfloat162 Ll = *(__nv_bfloat162*)&wvl;
                sVh[(cp * 2) * VP + row]     = Hh.x;
                sVh[(cp * 2 + 1) * VP + row] = Hh.y;
                sVl[(cp * 2) * VP + row]     = Ll.x;
                sVl[(cp * 2 + 1) * VP + row] = Ll.y;
            }
        }
        __syncthreads();

        // S = Q @ K^T  (8 n-frags x 5 k-chunks x 3 products)
        float sacc[8][4];
#pragma unroll
        for (int ni = 0; ni < 8; ni++)
#pragma unroll
            for (int q = 0; q < 4; q++) sacc[ni][q] = 0.f;

#pragma unroll
        for (int kc = 0; kc < 5; kc++) {
            const int ko = kc * 16 + t4 * 2;
            const int qr = wm + g;
            uint32_t ah[4], al[4];
            ah[0] = *(const uint32_t*)&sQh[qr * QP + ko];
            ah[1] = *(const uint32_t*)&sQh[(qr + 8) * QP + ko];
            ah[2] = *(const uint32_t*)&sQh[qr * QP + ko + 8];
            ah[3] = *(const uint32_t*)&sQh[(qr + 8) * QP + ko + 8];
            al[0] = *(const uint32_t*)&sQl[qr * QP + ko];
            al[1] = *(const uint32_t*)&sQl[(qr + 8) * QP + ko];
            al[2] = *(const uint32_t*)&sQl[qr * QP + ko + 8];
            al[3] = *(const uint32_t*)&sQl[(qr + 8) * QP + ko + 8];
#pragma unroll
            for (int ni = 0; ni < 8; ni++) {
                const int kr = ni * 8 + g;
                uint32_t bh2[2], bl2[2];
                bh2[0] = *(const uint32_t*)&sKh[kr * QP + ko];
                bh2[1] = *(const uint32_t*)&sKh[kr * QP + ko + 8];
                bl2[0] = *(const uint32_t*)&sKl[kr * QP + ko];
                bl2[1] = *(const uint32_t*)&sKl[kr * QP + ko + 8];
                mma16816(sacc[ni], ah, bh2);
                mma16816(sacc[ni], ah, bl2);
                mma16816(sacc[ni], al, bh2);
            }
        }

        // scale + causal mask (additive -10000, matches reference)
        const bool edge = (kb >= 2 * qt);
#pragma unroll
        for (int ni = 0; ni < 8; ni++) {
#pragma unroll
            for (int q = 0; q < 4; q++) {
                float v = sacc[ni][q] * scale;
                if (edge) {
                    const int key = kb * 64 + ni * 8 + t4 * 2 + (q & 1);
                    const int qr  = (q < 2) ? gr0 : gr1;
                    if (key > qr) v -= 10000.f;
                }
                sacc[ni][q] = v;
            }
        }

        // online softmax (rows gr0 and gr1 per thread, quad-replicated)
        float mx0 = -1e30f, mx1 = -1e30f;
#pragma unroll
        for (int ni = 0; ni < 8; ni++) {
            mx0 = fmaxf(mx0, fmaxf(sacc[ni][0], sacc[ni][1]));
            mx1 = fmaxf(mx1, fmaxf(sacc[ni][2], sacc[ni][3]));
        }
        mx0 = fmaxf(mx0, __shfl_xor_sync(0xffffffffu, mx0, 1));
        mx0 = fmaxf(mx0, __shfl_xor_sync(0xffffffffu, mx0, 2));
        mx1 = fmaxf(mx1, __shfl_xor_sync(0xffffffffu, mx1, 1));
        mx1 = fmaxf(mx1, __shfl_xor_sync(0xffffffffu, mx1, 2));
        const float mn0 = fmaxf(m0, mx0), mn1 = fmaxf(m1, mx1);
        const float c0 = __expf(m0 - mn0), c1 = __expf(m1 - mn1);
        float s0 = 0.f, s1 = 0.f;
#pragma unroll
        for (int ni = 0; ni < 8; ni++) {
            sacc[ni][0] = __expf(sacc[ni][0] - mn0);
            sacc[ni][1] = __expf(sacc[ni][1] - mn0);
            sacc[ni][2] = __expf(sacc[ni][2] - mn1);
            sacc[ni][3] = __expf(sacc[ni][3] - mn1);
            s0 += sacc[ni][0] + sacc[ni][1];
            s1 += sacc[ni][2] + sacc[ni][3];
        }
        s0 += __shfl_xor_sync(0xffffffffu, s0, 1);
        s0 += __shfl_xor_sync(0xffffffffu, s0, 2);
        s1 += __shfl_xor_sync(0xffffffffu, s1, 1);
        s1 += __shfl_xor_sync(0xffffffffu, s1, 2);
        l0 = l0 * c0 + s0;  m0 = mn0;
        l1 = l1 * c1 + s1;  m1 = mn1;

#pragma unroll
        for (int nj = 0; nj < 10; nj++) {
            oacc[nj][0] *= c0; oacc[nj][1] *= c0;
            oacc[nj][2] *= c1; oacc[nj][3] *= c1;
        }

        // O += P @ V  (P stays in registers; repack S accum -> A frags)
#pragma unroll
        for (int kc2 = 0; kc2 < 4; kc2++) {
            uint32_t aph[4], apl[4];
            split_pack2(sacc[2 * kc2][0],     sacc[2 * kc2][1],     aph[0], apl[0]);
            split_pack2(sacc[2 * kc2][2],     sacc[2 * kc2][3],     aph[1], apl[1]);
            split_pack2(sacc[2 * kc2 + 1][0], sacc[2 * kc2 + 1][1], aph[2], apl[2]);
            split_pack2(sacc[2 * kc2 + 1][2], sacc[2 * kc2 + 1][3], aph[3], apl[3]);
            const int ko2 = kc2 * 16 + t4 * 2;
#pragma unroll
            for (int nj = 0; nj < 10; nj++) {
                const int vr = nj * 8 + g;
                uint32_t bh2[2], bl2[2];
                bh2[0] = *(const uint32_t*)&sVh[vr * VP + ko2];
                bh2[1] = *(const uint32_t*)&sVh[vr * VP + ko2 + 8];
                bl2[0] = *(const uint32_t*)&sVl[vr * VP + ko2];
                bl2[1] = *(const uint32_t*)&sVl[vr * VP + ko2 + 8];
                mma16816(oacc[nj], aph, bh2);
                mma16816(oacc[nj], aph, bl2);
                mma16816(oacc[nj], apl, bh2);
            }
        }
    }

    // Normalize and write ctx as bf16 hi/lo split (row-major [MROWS, DD])
    const float inv0 = 1.f / l0, inv1 = 1.f / l1;
    const size_t r0idx = ((size_t)b * SS + qbase + wm + g) * DD + h * DP;
    const size_t r1idx = r0idx + 8 * DD;
#pragma unroll
    for (int nj = 0; nj < 10; nj++) {
        const int col = nj * 8 + t4 * 2;
        uint32_t h0, l0p, h1, l1p;
        split_pack2(oacc[nj][0] * inv0, oacc[nj][1] * inv0, h0, l0p);
        split_pack2(oacc[nj][2] * inv1, oacc[nj][3] * inv1, h1, l1p);
        *(uint32_t*)&g_Chi[r0idx + col] = h0;
        *(uint32_t*)&g_Clo[r0idx + col] = l0p;
        *(uint32_t*)&g_Chi[r1idx + col] = h1;
        *(uint32_t*)&g_Clo[r1idx + col] = l1p;
    }
}

// ---------------------------------------------------------------------------
extern "C" void kernel_launch(void* const* d_in, const int* in_sizes, int n_in,
                              void* d_out, int out_size)
{
    const float* x  = (const float*)d_in[0];
    const float* Wq = (const float*)d_in[2];
    const float* bq = (const float*)d_in[3];
    const float* Wk = (const float*)d_in[4];
    const float* bk = (const float*)d_in[5];
    const float* Wv = (const float*)d_in[6];
    const float* bv = (const float*)d_in[7];
    const float* Wo = (const float*)d_in[8];
    const float* bo = (const float*)d_in[9];
    float* out = (float*)d_out;

    __nv_bfloat16 *xhi, *xlo, *wthi, *wtlo, *chi, *clo;
    cudaGetSymbolAddress((void**)&xhi, g_Xhi);
    cudaGetSymbolAddress((void**)&xlo, g_Xlo);
    cudaGetSymbolAddress((void**)&wthi, g_WThi);
    cudaGetSymbolAddress((void**)&wtlo, g_WTlo);
    cudaGetSymbolAddress((void**)&chi, g_Chi);
    cudaGetSymbolAddress((void**)&clo, g_Clo);

    // 1. split x
    {
        const int n2 = MROWS * DD / 2;
        split_kernel<<<(n2 + 255) / 256, 256>>>(x, xhi, xlo, n2);
    }
    // 2. transpose+split weights
    wsplit_kernel<<<dim3(40, 40), dim3(32, 8)>>>(Wq, 0);
    wsplit_kernel<<<dim3(40, 40), dim3(32, 8)>>>(Wk, DD);
    wsplit_kernel<<<dim3(40, 40), dim3(32, 8)>>>(Wv, 2 * DD);
    wsplit_kernel<<<dim3(40, 40), dim3(32, 8)>>>(Wo, 3 * DD);

    // 3. QKV projection (HMMA) -> split bf16 Q/K/V
    mma_gemm_kernel<<<dim3(NQKV / 128, MROWS / 128), 256>>>(
        xhi, xlo, wthi, wtlo, bq, bk, bv, 0, nullptr);

    // 4. attention (HMMA flash) -> split bf16 ctx
    {
        const int smem_bytes = ATT_SMEM_BF16 * (int)sizeof(__nv_bfloat16);
        cudaFuncSetAttribute(attn_mma_kernel, cudaFuncAttributeMaxDynamicSharedMemorySize, smem_bytes);
        attn_mma_kernel<<<dim3(SS / 128, HH, BB), 256, smem_bytes>>>();
    }

    // 5. output projection (HMMA)
    mma_gemm_kernel<<<dim3(DD / 128, MROWS / 128), 256>>>(
        chi, clo, wthi + (size_t)3 * DD * DD, wtlo + (size_t)3 * DD * DD,
        bo, nullptr, nullptr, 1, out);
}

// round 7
// speedup vs baseline: 1.8423x; 1.1440x over previous
#include <cuda_runtime.h>
#include <cuda_bf16.h>
#include <cstdint>
#include <math.h>

// Problem constants
#define BB 2
#define SS 2048
#define DD 1280
#define HH 16
#define DP 80
#define MROWS (BB * SS)          // 4096
#define NQKV (3 * DD)            // 3840

// ---------------------------------------------------------------------------
// Device scratch (allocation-free rule)
// ---------------------------------------------------------------------------
__device__ __nv_bfloat16 g_Qhi[BB * HH * SS * DP];
__device__ __nv_bfloat16 g_Qlo[BB * HH * SS * DP];
__device__ __nv_bfloat16 g_Khi[BB * HH * SS * DP];
__device__ __nv_bfloat16 g_Klo[BB * HH * SS * DP];
__device__ __nv_bfloat16 g_Vhi[BB * HH * SS * DP];
__device__ __nv_bfloat16 g_Vlo[BB * HH * SS * DP];

__device__ __nv_bfloat16 g_Xhi[MROWS * DD];
__device__ __nv_bfloat16 g_Xlo[MROWS * DD];
__device__ __nv_bfloat16 g_WThi[4 * DD * DD];   // rows [0,3840)=Wq,Wk,Wv^T ; [3840,5120)=Wo^T
__device__ __nv_bfloat16 g_WTlo[4 * DD * DD];
__device__ __nv_bfloat16 g_Chi[MROWS * DD];
__device__ __nv_bfloat16 g_Clo[MROWS * DD];

// ---------------------------------------------------------------------------
// mma.sync + ldmatrix helpers (portable to sm_103)
// ---------------------------------------------------------------------------
__device__ __forceinline__ void mma16816(float* c, const uint32_t* a, const uint32_t* b) {
    asm volatile(
        "mma.sync.aligned.m16n8k16.row.col.f32.bf16.bf16.f32 "
        "{%0,%1,%2,%3}, {%4,%5,%6,%7}, {%8,%9}, {%0,%1,%2,%3};"
        : "+f"(c[0]), "+f"(c[1]), "+f"(c[2]), "+f"(c[3])
        : "r"(a[0]), "r"(a[1]), "r"(a[2]), "r"(a[3]), "r"(b[0]), "r"(b[1]));
}

__device__ __forceinline__ void ldsm_x4(uint32_t* r, uint32_t addr) {
    asm volatile("ldmatrix.sync.aligned.m8n8.x4.shared.b16 {%0,%1,%2,%3}, [%4];"
        : "=r"(r[0]), "=r"(r[1]), "=r"(r[2]), "=r"(r[3]) : "r"(addr));
}
__device__ __forceinline__ void ldsm_x4_t(uint32_t* r, uint32_t addr) {
    asm volatile("ldmatrix.sync.aligned.m8n8.x4.trans.shared.b16 {%0,%1,%2,%3}, [%4];"
        : "=r"(r[0]), "=r"(r[1]), "=r"(r[2]), "=r"(r[3]) : "r"(addr));
}

__device__ __forceinline__ uint32_t smem_u32(const void* p) {
    return (uint32_t)__cvta_generic_to_shared(p);
}

// split a,b -> packed bf16x2 hi and lo
__device__ __forceinline__ void split_pack2(float a, float b, uint32_t& hi, uint32_t& lo) {
    __nv_bfloat16 ha = __float2bfloat16(a), hb = __float2bfloat16(b);
    __nv_bfloat16 la = __float2bfloat16(a - __bfloat162float(ha));
    __nv_bfloat16 lb = __float2bfloat16(b - __bfloat162float(hb));
    __nv_bfloat162 H = __nv_bfloat162(ha, hb);
    __nv_bfloat162 L = __nv_bfloat162(la, lb);
    hi = *(uint32_t*)&H;
    lo = *(uint32_t*)&L;
}

// ---------------------------------------------------------------------------
// fp32 -> (bf16 hi, bf16 lo) elementwise split
// ---------------------------------------------------------------------------
__global__ __launch_bounds__(256) void split_kernel(const float* __restrict__ src,
                                                    __nv_bfloat16* __restrict__ hi,
                                                    __nv_bfloat16* __restrict__ lo,
                                                    int n2) {
    int i = blockIdx.x * blockDim.x + threadIdx.x;
    if (i >= n2) return;
    float2 v = *(const float2*)(src + 2 * (size_t)i);
    __nv_bfloat16 h0 = __float2bfloat16(v.x);
    __nv_bfloat16 h1 = __float2bfloat16(v.y);
    __nv_bfloat16 l0 = __float2bfloat16(v.x - __bfloat162float(h0));
    __nv_bfloat16 l1 = __float2bfloat16(v.y - __bfloat162float(h1));
    *(__nv_bfloat162*)(hi + 2 * (size_t)i) = __nv_bfloat162(h0, h1);
    *(__nv_bfloat162*)(lo + 2 * (size_t)i) = __nv_bfloat162(l0, l1);
}

// ---------------------------------------------------------------------------
// W [K=1280, N=1280] row-major -> W^T split into g_WThi/lo rows [ro, ro+1280)
// ---------------------------------------------------------------------------
__global__ __launch_bounds__(256) void wsplit_kernel(const float* __restrict__ W, int ro) {
    __shared__ float tile[32][33];
    const int tx = threadIdx.x;
    const int ty = threadIdx.y;
    const int n0 = blockIdx.x * 32;
    const int k0 = blockIdx.y * 32;
#pragma unroll
    for (int q = 0; q < 4; q++)
        tile[ty + q * 8][tx] = W[(size_t)(k0 + ty + q * 8) * DD + n0 + tx];
    __syncthreads();
#pragma unroll
    for (int q = 0; q < 4; q++) {
        const int nn = n0 + ty + q * 8;
        const int kk = k0 + tx;
        float v = tile[tx][ty + q * 8];
        __nv_bfloat16 h = __float2bfloat16(v);
        __nv_bfloat16 l = __float2bfloat16(v - __bfloat162float(h));
        g_WThi[(size_t)(ro + nn) * DD + kk] = h;
        g_WTlo[(size_t)(ro + nn) * DD + kk] = l;
    }
}

// ---------------------------------------------------------------------------
// HMMA split-bf16 GEMM with ldmatrix fragment feeds
// ---------------------------------------------------------------------------
#define BK2 32
#define AP 40      // smem pitch in bf16 (80B rows: ldmatrix conflict-free)

__global__ __launch_bounds__(256, 2) void mma_gemm_kernel(
    const __nv_bfloat16* __restrict__ Ahi, const __nv_bfloat16* __restrict__ Alo,
    const __nv_bfloat16* __restrict__ Bhi, const __nv_bfloat16* __restrict__ Blo,
    const float* __restrict__ b0, const float* __restrict__ b1, const float* __restrict__ b2,
    int mode, float* __restrict__ outp)
{
    __shared__ __nv_bfloat16 sAhi[128 * AP];
    __shared__ __nv_bfloat16 sAlo[128 * AP];
    __shared__ __nv_bfloat16 sBhi[128 * AP];
    __shared__ __nv_bfloat16 sBlo[128 * AP];

    const int t    = threadIdx.x;
    const int wid  = t >> 5;
    const int lane = t & 31;
    const int n0   = blockIdx.x * 128;
    const int m0   = blockIdx.y * 128;
    const int wm   = (wid >> 2) * 64;
    const int wn   = (wid & 3) * 32;
    const int g    = lane >> 2;
    const int t4   = lane & 3;

    // ldmatrix per-lane address components
    const int a_r = (lane & 7) + ((lane >> 3) & 1) * 8;   // row offset (matrix select)
    const int a_c = (lane >> 4) * 8;                      // k half select
    const int b_r = (lane & 7) + ((lane >> 4) & 1) * 8;   // n-frag within pair
    const int b_c = ((lane >> 3) & 1) * 8;                // k half select

    const uint32_t uAhi = smem_u32(sAhi), uAlo = smem_u32(sAlo);
    const uint32_t uBhi = smem_u32(sBhi), uBlo = smem_u32(sBlo);

    const int lr = t >> 1;
    const int lc = (t & 1) * 16;

    float acc[4][4][4];
#pragma unroll
    for (int mi = 0; mi < 4; mi++)
#pragma unroll
        for (int ni = 0; ni < 4; ni++)
#pragma unroll
            for (int q = 0; q < 4; q++) acc[mi][ni][q] = 0.f;

    for (int kc = 0; kc < DD / BK2; kc++) {
        const int kk = kc * BK2;
        const __nv_bfloat16* pAhi = Ahi + (size_t)(m0 + lr) * DD + kk + lc;
        const __nv_bfloat16* pAlo = Alo + (size_t)(m0 + lr) * DD + kk + lc;
        const __nv_bfloat16* pBhi = Bhi + (size_t)(n0 + lr) * DD + kk + lc;
        const __nv_bfloat16* pBlo = Blo + (size_t)(n0 + lr) * DD + kk + lc;
#pragma unroll
        for (int u = 0; u < 4; u++) {
            const int so = lr * AP + lc + u * 4;
            *(uint2*)&sAhi[so] = *(const uint2*)(pAhi + u * 4);
            *(uint2*)&sAlo[so] = *(const uint2*)(pAlo + u * 4);
            *(uint2*)&sBhi[so] = *(const uint2*)(pBhi + u * 4);
            *(uint2*)&sBlo[so] = *(const uint2*)(pBlo + u * 4);
        }
        __syncthreads();

#pragma unroll
        for (int ks = 0; ks < 2; ks++) {
            const int kb = ks * 16;
            uint32_t bh[4][2], bl[4][2];
#pragma unroll
            for (int p = 0; p < 2; p++) {
                const uint32_t off = (uint32_t)(((wn + p * 16 + b_r) * AP + kb + b_c) * 2);
                uint32_t r4[4];
                ldsm_x4(r4, uBhi + off);
                bh[2 * p][0] = r4[0]; bh[2 * p][1] = r4[1];
                bh[2 * p + 1][0] = r4[2]; bh[2 * p + 1][1] = r4[3];
                ldsm_x4(r4, uBlo + off);
                bl[2 * p][0] = r4[0]; bl[2 * p][1] = r4[1];
                bl[2 * p + 1][0] = r4[2]; bl[2 * p + 1][1] = r4[3];
            }
#pragma unroll
            for (int mi = 0; mi < 4; mi++) {
                const uint32_t off = (uint32_t)(((wm + mi * 16 + a_r) * AP + kb + a_c) * 2);
                uint32_t ah[4], al[4];
                ldsm_x4(ah, uAhi + off);
                ldsm_x4(al, uAlo + off);
#pragma unroll
                for (int ni = 0; ni < 4; ni++) {
                    mma16816(acc[mi][ni], ah, bh[ni]);
                    mma16816(acc[mi][ni], ah, bl[ni]);
                    mma16816(acc[mi][ni], al, bh[ni]);
                }
            }
        }
        __syncthreads();
    }

    // Epilogue
#pragma unroll
    for (int mi = 0; mi < 4; mi++) {
        const int r0 = m0 + wm + mi * 16 + g;
#pragma unroll
        for (int ni = 0; ni < 4; ni++) {
            const int cg0 = n0 + wn + ni * 8 + t4 * 2;
#pragma unroll
            for (int q = 0; q < 4; q++) {
                const int row = r0 + (q >> 1) * 8;
                const int cg  = cg0 + (q & 1);
                const float v = acc[mi][ni][q];
                if (mode == 0) {
                    const int which = cg / DD;
                    const int cl    = cg - which * DD;
                    const int head  = cl / DP;
                    const int dd    = cl - head * DP;
                    const float val = v + (which == 0 ? b0 : which == 1 ? b1 : b2)[cl];
                    __nv_bfloat16* dh = (which == 0) ? g_Qhi : (which == 1) ? g_Khi : g_Vhi;
                    __nv_bfloat16* dl = (which == 0) ? g_Qlo : (which == 1) ? g_Klo : g_Vlo;
                    const int b_ = row >> 11;
                    const int s_ = row & 2047;
                    const size_t idx = (((size_t)b_ * HH + head) * SS + s_) * DP + dd;
                    __nv_bfloat16 hv = __float2bfloat16(val);
                    dh[idx] = hv;
                    dl[idx] = __float2bfloat16(val - __bfloat162float(hv));
                } else {
                    outp[(size_t)row * DD + cg] = v + b0[cg];
                }
            }
        }
    }
}

// ---------------------------------------------------------------------------
// HMMA flash attention with ldmatrix feeds; V via ldmatrix.trans (no smem
// transpose). 128 q-rows x 64-key tiles, 8 warps x 16 rows.
// ---------------------------------------------------------------------------
#define QP 88     // smem pitch bf16 (176B rows: ldmatrix conflict-free)
#define ATT_SMEM_BF16 (2 * (128 + 64 + 64) * QP)

__global__ __launch_bounds__(256, 2) void attn_mma_kernel()
{
    extern __shared__ __nv_bfloat16 sm[];
    __nv_bfloat16* sQh = sm;
    __nv_bfloat16* sQl = sQh + 128 * QP;
    __nv_bfloat16* sKh = sQl + 128 * QP;
    __nv_bfloat16* sKl = sKh + 64 * QP;
    __nv_bfloat16* sVh = sKl + 64 * QP;   // row-major [64][QP] like K
    __nv_bfloat16* sVl = sVh + 64 * QP;

    const int t    = threadIdx.x;
    const int wid  = t >> 5;
    const int lane = t & 31;
    const int g    = lane >> 2;
    const int t4   = lane & 3;
    const int qt   = (int)(gridDim.x - 1) - (int)blockIdx.x;
    const int h    = blockIdx.y;
    const int b    = blockIdx.z;
    const size_t bh_off = ((size_t)b * HH + h) * SS * DP;
    const int qbase = qt * 128;
    const int wm    = wid * 16;
    const float scale = 0.11180339887498948f;   // 1/sqrt(80)

    // ldmatrix lane address components
    const int a_r = (lane & 7) + ((lane >> 3) & 1) * 8;
    const int a_c = (lane >> 4) * 8;
    const int b_r = (lane & 7) + ((lane >> 4) & 1) * 8;
    const int b_c = ((lane >> 3) & 1) * 8;
    // trans (V): source rows = keys, cols = d
    const int v_r = (lane & 7) + ((lane >> 3) & 1) * 8;
    const int v_c = ((lane >> 4) & 1) * 8;

    const uint32_t uQh = smem_u32(sQh), uQl = smem_u32(sQl);
    const uint32_t uKh = smem_u32(sKh), uKl = smem_u32(sKl);
    const uint32_t uVh = smem_u32(sVh), uVl = smem_u32(sVl);

    // Load Q tile (128 x 80), hi+lo
    {
        const uint32_t* gh = (const uint32_t*)g_Qhi + (bh_off + (size_t)qbase * DP) / 2;
        const uint32_t* gl = (const uint32_t*)g_Qlo + (bh_off + (size_t)qbase * DP) / 2;
        for (int i = t; i < 128 * 40; i += 256) {
            const int row = i / 40, cp = i % 40;
            *(uint32_t*)&sQh[row * QP + cp * 2] = gh[row * 40 + cp];
            *(uint32_t*)&sQl[row * QP + cp * 2] = gl[row * 40 + cp];
        }
    }

    float oacc[10][4];
#pragma unroll
    for (int nj = 0; nj < 10; nj++)
#pragma unroll
        for (int q = 0; q < 4; q++) oacc[nj][q] = 0.f;
    float m0 = -1e30f, m1 = -1e30f, l0 = 0.f, l1 = 0.f;

    const int gr0 = qbase + wm + g;
    const int gr1 = gr0 + 8;
    const int ktiles = 2 * qt + 2;

    for (int kb = 0; kb < ktiles; kb++) {
        __syncthreads();
        // Load K and V (both 64x80 row-major), hi+lo
        {
            const size_t koff = (bh_off + (size_t)kb * 64 * DP) / 2;
            const uint32_t* kh = (const uint32_t*)g_Khi + koff;
            const uint32_t* kl = (const uint32_t*)g_Klo + koff;
            const uint32_t* vh = (const uint32_t*)g_Vhi + koff;
            const uint32_t* vl = (const uint32_t*)g_Vlo + koff;
            for (int i = t; i < 64 * 40; i += 256) {
                const int row = i / 40, cp = i % 40;
                *(uint32_t*)&sKh[row * QP + cp * 2] = kh[row * 40 + cp];
                *(uint32_t*)&sKl[row * QP + cp * 2] = kl[row * 40 + cp];
                *(uint32_t*)&sVh[row * QP + cp * 2] = vh[row * 40 + cp];
                *(uint32_t*)&sVl[row * QP + cp * 2] = vl[row * 40 + cp];
            }
        }
        __syncthreads();

        // S = Q @ K^T
        float sacc[8][4];
#pragma unroll
        for (int ni = 0; ni < 8; ni++)
#pragma unroll
            for (int q = 0; q < 4; q++) sacc[ni][q] = 0.f;

#pragma unroll
        for (int kc = 0; kc < 5; kc++) {
            const int ko = kc * 16;
            uint32_t ah[4], al[4];
            ldsm_x4(ah, uQh + (uint32_t)(((wm + a_r) * QP + ko + a_c) * 2));
            ldsm_x4(al, uQl + (uint32_t)(((wm + a_r) * QP + ko + a_c) * 2));
#pragma unroll
            for (int p = 0; p < 4; p++) {
                const uint32_t off = (uint32_t)(((p * 16 + b_r) * QP + ko + b_c) * 2);
                uint32_t rh[4], rl[4];
                ldsm_x4(rh, uKh + off);
                ldsm_x4(rl, uKl + off);
                mma16816(sacc[2 * p],     ah, rh);      // b = {rh[0], rh[1]}
                mma16816(sacc[2 * p],     ah, rl);
                mma16816(sacc[2 * p],     al, rh);
                mma16816(sacc[2 * p + 1], ah, rh + 2);
                mma16816(sacc[2 * p + 1], ah, rl + 2);
                mma16816(sacc[2 * p + 1], al, rh + 2);
            }
        }

        // scale + causal mask (additive -10000, matches reference)
        const bool edge = (kb >= 2 * qt);
#pragma unroll
        for (int ni = 0; ni < 8; ni++) {
#pragma unroll
            for (int q = 0; q < 4; q++) {
                float v = sacc[ni][q] * scale;
                if (edge) {
                    const int key = kb * 64 + ni * 8 + t4 * 2 + (q & 1);
                    const int qr  = (q < 2) ? gr0 : gr1;
                    if (key > qr) v -= 10000.f;
                }
                sacc[ni][q] = v;
            }
        }

        // online softmax
        float mx0 = -1e30f, mx1 = -1e30f;
#pragma unroll
        for (int ni = 0; ni < 8; ni++) {
            mx0 = fmaxf(mx0, fmaxf(sacc[ni][0], sacc[ni][1]));
            mx1 = fmaxf(mx1, fmaxf(sacc[ni][2], sacc[ni][3]));
        }
        mx0 = fmaxf(mx0, __shfl_xor_sync(0xffffffffu, mx0, 1));
        mx0 = fmaxf(mx0, __shfl_xor_sync(0xffffffffu, mx0, 2));
        mx1 = fmaxf(mx1, __shfl_xor_sync(0xffffffffu, mx1, 1));
        mx1 = fmaxf(mx1, __shfl_xor_sync(0xffffffffu, mx1, 2));
        const float mn0 = fmaxf(m0, mx0), mn1 = fmaxf(m1, mx1);
        const float c0 = __expf(m0 - mn0), c1 = __expf(m1 - mn1);
        float s0 = 0.f, s1 = 0.f;
#pragma unroll
        for (int ni = 0; ni < 8; ni++) {
            sacc[ni][0] = __expf(sacc[ni][0] - mn0);
            sacc[ni][1] = __expf(sacc[ni][1] - mn0);
            sacc[ni][2] = __expf(sacc[ni][2] - mn1);
            sacc[ni][3] = __expf(sacc[ni][3] - mn1);
            s0 += sacc[ni][0] + sacc[ni][1];
            s1 += sacc[ni][2] + sacc[ni][3];
        }
        s0 += __shfl_xor_sync(0xffffffffu, s0, 1);
        s0 += __shfl_xor_sync(0xffffffffu, s0, 2);
        s1 += __shfl_xor_sync(0xffffffffu, s1, 1);
        s1 += __shfl_xor_sync(0xffffffffu, s1, 2);
        l0 = l0 * c0 + s0;  m0 = mn0;
        l1 = l1 * c1 + s1;  m1 = mn1;

#pragma unroll
        for (int nj = 0; nj < 10; nj++) {
            oacc[nj][0] *= c0; oacc[nj][1] *= c0;
            oacc[nj][2] *= c1; oacc[nj][3] *= c1;
        }

        // O += P @ V  (P in regs; V^T fragments via ldmatrix.trans)
#pragma unroll
        for (int kc2 = 0; kc2 < 4; kc2++) {
            uint32_t aph[4], apl[4];
            split_pack2(sacc[2 * kc2][0],     sacc[2 * kc2][1],     aph[0], apl[0]);
            split_pack2(sacc[2 * kc2][2],     sacc[2 * kc2][3],     aph[1], apl[1]);
            split_pack2(sacc[2 * kc2 + 1][0], sacc[2 * kc2 + 1][1], aph[2], apl[2]);
            split_pack2(sacc[2 * kc2 + 1][2], sacc[2 * kc2 + 1][3], aph[3], apl[3]);
            const int ko2 = kc2 * 16;
#pragma unroll
            for (int p = 0; p < 5; p++) {
                const uint32_t off = (uint32_t)(((ko2 + v_r) * QP + p * 16 + v_c) * 2);
                uint32_t rh[4], rl[4];
                ldsm_x4_t(rh, uVh + off);
                ldsm_x4_t(rl, uVl + off);
                mma16816(oacc[2 * p],     aph, rh);
                mma16816(oacc[2 * p],     aph, rl);
                mma16816(oacc[2 * p],     apl, rh);
                mma16816(oacc[2 * p + 1], aph, rh + 2);
                mma16816(oacc[2 * p + 1], aph, rl + 2);
                mma16816(oacc[2 * p + 1], apl, rh + 2);
            }
        }
    }

    // Normalize and write ctx as bf16 hi/lo split (row-major [MROWS, DD])
    const float inv0 = 1.f / l0, inv1 = 1.f / l1;
    const size_t r0idx = ((size_t)b * SS + qbase + wm + g) * DD + h * DP;
    const size_t r1idx = r0idx + 8 * DD;
#pragma unroll
    for (int nj = 0; nj < 10; nj++) {
        const int col = nj * 8 + t4 * 2;
        uint32_t h0, l0p, h1, l1p;
        split_pack2(oacc[nj][0] * inv0, oacc[nj][1] * inv0, h0, l0p);
        split_pack2(oacc[nj][2] * inv1, oacc[nj][3] * inv1, h1, l1p);
        *(uint32_t*)&g_Chi[r0idx + col] = h0;
        *(uint32_t*)&g_Clo[r0idx + col] = l0p;
        *(uint32_t*)&g_Chi[r1idx + col] = h1;
        *(uint32_t*)&g_Clo[r1idx + col] = l1p;
    }
}

// ---------------------------------------------------------------------------
extern "C" void kernel_launch(void* const* d_in, const int* in_sizes, int n_in,
                              void* d_out, int out_size)
{
    const float* x  = (const float*)d_in[0];
    const float* Wq = (const float*)d_in[2];
    const float* bq = (const float*)d_in[3];
    const float* Wk = (const float*)d_in[4];
    const float* bk = (const float*)d_in[5];
    const float* Wv = (const float*)d_in[6];
    const float* bv = (const float*)d_in[7];
    const float* Wo = (const float*)d_in[8];
    const float* bo = (const float*)d_in[9];
    float* out = (float*)d_out;

    __nv_bfloat16 *xhi, *xlo, *wthi, *wtlo, *chi, *clo;
    cudaGetSymbolAddress((void**)&xhi, g_Xhi);
    cudaGetSymbolAddress((void**)&xlo, g_Xlo);
    cudaGetSymbolAddress((void**)&wthi, g_WThi);
    cudaGetSymbolAddress((void**)&wtlo, g_WTlo);
    cudaGetSymbolAddress((void**)&chi, g_Chi);
    cudaGetSymbolAddress((void**)&clo, g_Clo);

    // 1. split x
    {
        const int n2 = MROWS * DD / 2;
        split_kernel<<<(n2 + 255) / 256, 256>>>(x, xhi, xlo, n2);
    }
    // 2. transpose+split weights
    wsplit_kernel<<<dim3(40, 40), dim3(32, 8)>>>(Wq, 0);
    wsplit_kernel<<<dim3(40, 40), dim3(32, 8)>>>(Wk, DD);
    wsplit_kernel<<<dim3(40, 40), dim3(32, 8)>>>(Wv, 2 * DD);
    wsplit_kernel<<<dim3(40, 40), dim3(32, 8)>>>(Wo, 3 * DD);

    // 3. QKV projection (HMMA + ldmatrix)
    mma_gemm_kernel<<<dim3(NQKV / 128, MROWS / 128), 256>>>(
        xhi, xlo, wthi, wtlo, bq, bk, bv, 0, nullptr);

    // 4. attention (HMMA flash + ldmatrix)
    {
        const int smem_bytes = ATT_SMEM_BF16 * (int)sizeof(__nv_bfloat16);
        cudaFuncSetAttribute(attn_mma_kernel, cudaFuncAttributeMaxDynamicSharedMemorySize, smem_bytes);
        attn_mma_kernel<<<dim3(SS / 128, HH, BB), 256, smem_bytes>>>();
    }

    // 5. output projection (HMMA + ldmatrix)
    mma_gemm_kernel<<<dim3(DD / 128, MROWS / 128), 256>>>(
        chi, clo, wthi + (size_t)3 * DD * DD, wtlo + (size_t)3 * DD * DD,
        bo, nullptr, nullptr, 1, out);
}

// round 8
// speedup vs baseline: 2.5942x; 1.4081x over previous
#include <cuda_runtime.h>
#include <cuda_bf16.h>
#include <cstdint>
#include <math.h>

// Problem constants
#define BB 2
#define SS 2048
#define DD 1280
#define HH 16
#define DP 80
#define MROWS (BB * SS)          // 4096
#define NQKV (3 * DD)            // 3840

// ---------------------------------------------------------------------------
// Device scratch (allocation-free rule)
// ---------------------------------------------------------------------------
__device__ __nv_bfloat16 g_Qhi[BB * HH * SS * DP];
__device__ __nv_bfloat16 g_Qlo[BB * HH * SS * DP];
__device__ __nv_bfloat16 g_Khi[BB * HH * SS * DP];
__device__ __nv_bfloat16 g_Klo[BB * HH * SS * DP];
__device__ __nv_bfloat16 g_Vhi[BB * HH * SS * DP];
__device__ __nv_bfloat16 g_Vlo[BB * HH * SS * DP];

__device__ __nv_bfloat16 g_Xhi[MROWS * DD];
__device__ __nv_bfloat16 g_Xlo[MROWS * DD];
__device__ __nv_bfloat16 g_WThi[4 * DD * DD];   // rows [0,3840)=Wq,Wk,Wv^T ; [3840,5120)=Wo^T
__device__ __nv_bfloat16 g_WTlo[4 * DD * DD];
__device__ __nv_bfloat16 g_Chi[MROWS * DD];
__device__ __nv_bfloat16 g_Clo[MROWS * DD];

// ---------------------------------------------------------------------------
// mma.sync + ldmatrix + cp.async helpers (portable to sm_103)
// ---------------------------------------------------------------------------
__device__ __forceinline__ void mma16816(float* c, const uint32_t* a, const uint32_t* b) {
    asm volatile(
        "mma.sync.aligned.m16n8k16.row.col.f32.bf16.bf16.f32 "
        "{%0,%1,%2,%3}, {%4,%5,%6,%7}, {%8,%9}, {%0,%1,%2,%3};"
        : "+f"(c[0]), "+f"(c[1]), "+f"(c[2]), "+f"(c[3])
        : "r"(a[0]), "r"(a[1]), "r"(a[2]), "r"(a[3]), "r"(b[0]), "r"(b[1]));
}

__device__ __forceinline__ void ldsm_x4(uint32_t* r, uint32_t addr) {
    asm volatile("ldmatrix.sync.aligned.m8n8.x4.shared.b16 {%0,%1,%2,%3}, [%4];"
        : "=r"(r[0]), "=r"(r[1]), "=r"(r[2]), "=r"(r[3]) : "r"(addr));
}
__device__ __forceinline__ void ldsm_x4_t(uint32_t* r, uint32_t addr) {
    asm volatile("ldmatrix.sync.aligned.m8n8.x4.trans.shared.b16 {%0,%1,%2,%3}, [%4];"
        : "=r"(r[0]), "=r"(r[1]), "=r"(r[2]), "=r"(r[3]) : "r"(addr));
}

__device__ __forceinline__ uint32_t smem_u32(const void* p) {
    return (uint32_t)__cvta_generic_to_shared(p);
}

__device__ __forceinline__ void cp_async16(uint32_t dst, const void* src) {
    asm volatile("cp.async.ca.shared.global [%0], [%1], 16;" :: "r"(dst), "l"(src));
}
__device__ __forceinline__ void cp_commit() {
    asm volatile("cp.async.commit_group;");
}

// split a,b -> packed bf16x2 hi and lo
__device__ __forceinline__ void split_pack2(float a, float b, uint32_t& hi, uint32_t& lo) {
    __nv_bfloat16 ha = __float2bfloat16(a), hb = __float2bfloat16(b);
    __nv_bfloat16 la = __float2bfloat16(a - __bfloat162float(ha));
    __nv_bfloat16 lb = __float2bfloat16(b - __bfloat162float(hb));
    __nv_bfloat162 H = __nv_bfloat162(ha, hb);
    __nv_bfloat162 L = __nv_bfloat162(la, lb);
    hi = *(uint32_t*)&H;
    lo = *(uint32_t*)&L;
}

// ---------------------------------------------------------------------------
// fp32 -> (bf16 hi, bf16 lo) elementwise split
// ---------------------------------------------------------------------------
__global__ __launch_bounds__(256) void split_kernel(const float* __restrict__ src,
                                                    __nv_bfloat16* __restrict__ hi,
                                                    __nv_bfloat16* __restrict__ lo,
                                                    int n2) {
    int i = blockIdx.x * blockDim.x + threadIdx.x;
    if (i >= n2) return;
    float2 v = *(const float2*)(src + 2 * (size_t)i);
    __nv_bfloat16 h0 = __float2bfloat16(v.x);
    __nv_bfloat16 h1 = __float2bfloat16(v.y);
    __nv_bfloat16 l0 = __float2bfloat16(v.x - __bfloat162float(h0));
    __nv_bfloat16 l1 = __float2bfloat16(v.y - __bfloat162float(h1));
    *(__nv_bfloat162*)(hi + 2 * (size_t)i) = __nv_bfloat162(h0, h1);
    *(__nv_bfloat162*)(lo + 2 * (size_t)i) = __nv_bfloat162(l0, l1);
}

// ---------------------------------------------------------------------------
// W [K=1280, N=1280] row-major -> W^T split into g_WThi/lo rows [ro, ro+1280)
// ---------------------------------------------------------------------------
__global__ __launch_bounds__(256) void wsplit_kernel(const float* __restrict__ W, int ro) {
    __shared__ float tile[32][33];
    const int tx = threadIdx.x;
    const int ty = threadIdx.y;
    const int n0 = blockIdx.x * 32;
    const int k0 = blockIdx.y * 32;
#pragma unroll
    for (int q = 0; q < 4; q++)
        tile[ty + q * 8][tx] = W[(size_t)(k0 + ty + q * 8) * DD + n0 + tx];
    __syncthreads();
#pragma unroll
    for (int q = 0; q < 4; q++) {
        const int nn = n0 + ty + q * 8;
        const int kk = k0 + tx;
        float v = tile[tx][ty + q * 8];
        __nv_bfloat16 h = __float2bfloat16(v);
        __nv_bfloat16 l = __float2bfloat16(v - __bfloat162float(h));
        g_WThi[(size_t)(ro + nn) * DD + kk] = h;
        g_WTlo[(size_t)(ro + nn) * DD + kk] = l;
    }
}

// ---------------------------------------------------------------------------
// HMMA split-bf16 GEMM: ldmatrix feeds + cp.async 2-stage pipeline
// ---------------------------------------------------------------------------
#define BK2 32
#define AP 40                       // smem pitch in bf16 (80B rows)
#define GSTR (128 * AP)             // bf16 per array per stage
#define GEMM_SMEM_BYTES (2 * 4 * GSTR * 2)   // 2 stages x 4 arrays

__global__ __launch_bounds__(256, 2) void mma_gemm_kernel(
    const __nv_bfloat16* __restrict__ Ahi, const __nv_bfloat16* __restrict__ Alo,
    const __nv_bfloat16* __restrict__ Bhi, const __nv_bfloat16* __restrict__ Blo,
    const float* __restrict__ b0, const float* __restrict__ b1, const float* __restrict__ b2,
    int mode, float* __restrict__ outp)
{
    extern __shared__ __nv_bfloat16 dsm[];

    const int t    = threadIdx.x;
    const int wid  = t >> 5;
    const int lane = t & 31;
    const int n0   = blockIdx.x * 128;
    const int m0   = blockIdx.y * 128;
    const int wm   = (wid >> 2) * 64;
    const int wn   = (wid & 3) * 32;
    const int g    = lane >> 2;
    const int t4   = lane & 3;

    // ldmatrix per-lane address components
    const int a_r = (lane & 7) + ((lane >> 3) & 1) * 8;
    const int a_c = (lane >> 4) * 8;
    const int b_r = (lane & 7) + ((lane >> 4) & 1) * 8;
    const int b_c = ((lane >> 3) & 1) * 8;

    const uint32_t sbase = smem_u32(dsm);

    const int lr = t >> 1;
    const int lc = (t & 1) * 16;

    // global row pointers (k offset added per chunk)
    const __nv_bfloat16* rowA_hi = Ahi + (size_t)(m0 + lr) * DD + lc;
    const __nv_bfloat16* rowA_lo = Alo + (size_t)(m0 + lr) * DD + lc;
    const __nv_bfloat16* rowB_hi = Bhi + (size_t)(n0 + lr) * DD + lc;
    const __nv_bfloat16* rowB_lo = Blo + (size_t)(n0 + lr) * DD + lc;
    const uint32_t dst_off = (uint32_t)((lr * AP + lc) * 2);

    float acc[4][4][4];
#pragma unroll
    for (int mi = 0; mi < 4; mi++)
#pragma unroll
        for (int ni = 0; ni < 4; ni++)
#pragma unroll
            for (int q = 0; q < 4; q++) acc[mi][ni][q] = 0.f;

    const int KCH = DD / BK2;       // 40

    // prologue: stage 0 <- chunk 0
    {
        const uint32_t sb = sbase + dst_off;
        cp_async16(sb + 0 * GSTR * 2,      rowA_hi);
        cp_async16(sb + 0 * GSTR * 2 + 16, rowA_hi + 8);
        cp_async16(sb + 1 * GSTR * 2,      rowA_lo);
        cp_async16(sb + 1 * GSTR * 2 + 16, rowA_lo + 8);
        cp_async16(sb + 2 * GSTR * 2,      rowB_hi);
        cp_async16(sb + 2 * GSTR * 2 + 16, rowB_hi + 8);
        cp_async16(sb + 3 * GSTR * 2,      rowB_lo);
        cp_async16(sb + 3 * GSTR * 2 + 16, rowB_lo + 8);
        cp_commit();
    }

    for (int kc = 0; kc < KCH; kc++) {
        if (kc + 1 < KCH) {
            const int kk = (kc + 1) * BK2;
            const uint32_t sb = sbase + (uint32_t)(((kc + 1) & 1) * 4 * GSTR * 2) + dst_off;
            cp_async16(sb + 0 * GSTR * 2,      rowA_hi + kk);
            cp_async16(sb + 0 * GSTR * 2 + 16, rowA_hi + kk + 8);
            cp_async16(sb + 1 * GSTR * 2,      rowA_lo + kk);
            cp_async16(sb + 1 * GSTR * 2 + 16, rowA_lo + kk + 8);
            cp_async16(sb + 2 * GSTR * 2,      rowB_hi + kk);
            cp_async16(sb + 2 * GSTR * 2 + 16, rowB_hi + kk + 8);
            cp_async16(sb + 3 * GSTR * 2,      rowB_lo + kk);
            cp_async16(sb + 3 * GSTR * 2 + 16, rowB_lo + kk + 8);
            cp_commit();
            asm volatile("cp.async.wait_group 1;");
        } else {
            asm volatile("cp.async.wait_group 0;");
        }
        __syncthreads();

        const uint32_t st = sbase + (uint32_t)((kc & 1) * 4 * GSTR * 2);
        const uint32_t uAhi = st;
        const uint32_t uAlo = st + 1 * GSTR * 2;
        const uint32_t uBhi = st + 2 * GSTR * 2;
        const uint32_t uBlo = st + 3 * GSTR * 2;

#pragma unroll
        for (int ks = 0; ks < 2; ks++) {
            const int kb = ks * 16;
            uint32_t bh[4][2], bl[4][2];
#pragma unroll
            for (int p = 0; p < 2; p++) {
                const uint32_t off = (uint32_t)(((wn + p * 16 + b_r) * AP + kb + b_c) * 2);
                uint32_t r4[4];
                ldsm_x4(r4, uBhi + off);
                bh[2 * p][0] = r4[0]; bh[2 * p][1] = r4[1];
                bh[2 * p + 1][0] = r4[2]; bh[2 * p + 1][1] = r4[3];
                ldsm_x4(r4, uBlo + off);
                bl[2 * p][0] = r4[0]; bl[2 * p][1] = r4[1];
                bl[2 * p + 1][0] = r4[2]; bl[2 * p + 1][1] = r4[3];
            }
#pragma unroll
            for (int mi = 0; mi < 4; mi++) {
                const uint32_t off = (uint32_t)(((wm + mi * 16 + a_r) * AP + kb + a_c) * 2);
                uint32_t ah[4], al[4];
                ldsm_x4(ah, uAhi + off);
                ldsm_x4(al, uAlo + off);
#pragma unroll
                for (int ni = 0; ni < 4; ni++) {
                    mma16816(acc[mi][ni], ah, bh[ni]);
                    mma16816(acc[mi][ni], ah, bl[ni]);
                    mma16816(acc[mi][ni], al, bh[ni]);
                }
            }
        }
        __syncthreads();
    }

    // Epilogue
#pragma unroll
    for (int mi = 0; mi < 4; mi++) {
        const int r0 = m0 + wm + mi * 16 + g;
#pragma unroll
        for (int ni = 0; ni < 4; ni++) {
            const int cg0 = n0 + wn + ni * 8 + t4 * 2;
#pragma unroll
            for (int q = 0; q < 4; q++) {
                const int row = r0 + (q >> 1) * 8;
                const int cg  = cg0 + (q & 1);
                const float v = acc[mi][ni][q];
                if (mode == 0) {
                    const int which = cg / DD;
                    const int cl    = cg - which * DD;
                    const int head  = cl / DP;
                    const int dd    = cl - head * DP;
                    const float val = v + (which == 0 ? b0 : which == 1 ? b1 : b2)[cl];
                    __nv_bfloat16* dh = (which == 0) ? g_Qhi : (which == 1) ? g_Khi : g_Vhi;
                    __nv_bfloat16* dl = (which == 0) ? g_Qlo : (which == 1) ? g_Klo : g_Vlo;
                    const int b_ = row >> 11;
                    const int s_ = row & 2047;
                    const size_t idx = (((size_t)b_ * HH + head) * SS + s_) * DP + dd;
                    __nv_bfloat16 hv = __float2bfloat16(val);
                    dh[idx] = hv;
                    dl[idx] = __float2bfloat16(val - __bfloat162float(hv));
                } else {
                    outp[(size_t)row * DD + cg] = v + b0[cg];
                }
            }
        }
    }
}

// ---------------------------------------------------------------------------
// HMMA flash attention: ldmatrix feeds, cp.async K/V loads.
// 128 q-rows x 64-key tiles, 8 warps x 16 rows.
// ---------------------------------------------------------------------------
#define QP 88     // smem pitch bf16 (176B rows)
#define ATT_SMEM_BF16 (2 * (128 + 64 + 64) * QP)

__global__ __launch_bounds__(256, 2) void attn_mma_kernel()
{
    extern __shared__ __nv_bfloat16 sm[];
    __nv_bfloat16* sQh = sm;
    __nv_bfloat16* sQl = sQh + 128 * QP;
    __nv_bfloat16* sKh = sQl + 128 * QP;
    __nv_bfloat16* sKl = sKh + 64 * QP;
    __nv_bfloat16* sVh = sKl + 64 * QP;   // row-major [64][QP] like K
    __nv_bfloat16* sVl = sVh + 64 * QP;

    const int t    = threadIdx.x;
    const int wid  = t >> 5;
    const int lane = t & 31;
    const int g    = lane >> 2;
    const int t4   = lane & 3;
    const int qt   = (int)(gridDim.x - 1) - (int)blockIdx.x;
    const int h    = blockIdx.y;
    const int b    = blockIdx.z;
    const size_t bh_off = ((size_t)b * HH + h) * SS * DP;
    const int qbase = qt * 128;
    const int wm    = wid * 16;
    const float scale = 0.11180339887498948f;   // 1/sqrt(80)

    // ldmatrix lane address components
    const int a_r = (lane & 7) + ((lane >> 3) & 1) * 8;
    const int a_c = (lane >> 4) * 8;
    const int b_r = (lane & 7) + ((lane >> 4) & 1) * 8;
    const int b_c = ((lane >> 3) & 1) * 8;
    const int v_r = (lane & 7) + ((lane >> 3) & 1) * 8;
    const int v_c = ((lane >> 4) & 1) * 8;

    const uint32_t uQh = smem_u32(sQh), uQl = smem_u32(sQl);
    const uint32_t uKh = smem_u32(sKh), uKl = smem_u32(sKl);
    const uint32_t uVh = smem_u32(sVh), uVl = smem_u32(sVl);

    // Load Q tile (128 x 80), hi+lo
    {
        const uint32_t* gh = (const uint32_t*)g_Qhi + (bh_off + (size_t)qbase * DP) / 2;
        const uint32_t* gl = (const uint32_t*)g_Qlo + (bh_off + (size_t)qbase * DP) / 2;
        for (int i = t; i < 128 * 40; i += 256) {
            const int row = i / 40, cp = i % 40;
            *(uint32_t*)&sQh[row * QP + cp * 2] = gh[row * 40 + cp];
            *(uint32_t*)&sQl[row * QP + cp * 2] = gl[row * 40 + cp];
        }
    }

    float oacc[10][4];
#pragma unroll
    for (int nj = 0; nj < 10; nj++)
#pragma unroll
        for (int q = 0; q < 4; q++) oacc[nj][q] = 0.f;
    float m0 = -1e30f, m1 = -1e30f, l0 = 0.f, l1 = 0.f;

    const int gr0 = qbase + wm + g;
    const int gr1 = gr0 + 8;
    const int ktiles = 2 * qt + 2;

    for (int kb = 0; kb < ktiles; kb++) {
        __syncthreads();
        // cp.async K/V loads (each row = 160B = 10 x 16B)
        {
            const size_t kbyte = (bh_off + (size_t)kb * 64 * DP) * 2;
            const char* srcs[4] = {
                (const char*)g_Khi + kbyte, (const char*)g_Klo + kbyte,
                (const char*)g_Vhi + kbyte, (const char*)g_Vlo + kbyte };
            const uint32_t dsts[4] = { uKh, uKl, uVh, uVl };
#pragma unroll
            for (int it = 0; it < 10; it++) {
                const int idx = t + it * 256;          // 0..2559
                const int arr = idx / 640;
                const int rem = idx - arr * 640;
                const int row = rem / 10;
                const int c16 = rem - row * 10;
                cp_async16(dsts[arr] + (uint32_t)(row * (QP * 2) + c16 * 16),
                           srcs[arr] + (size_t)row * (DP * 2) + c16 * 16);
            }
            cp_commit();
            asm volatile("cp.async.wait_group 0;");
        }
        __syncthreads();

        // S = Q @ K^T
        float sacc[8][4];
#pragma unroll
        for (int ni = 0; ni < 8; ni++)
#pragma unroll
            for (int q = 0; q < 4; q++) sacc[ni][q] = 0.f;

#pragma unroll
        for (int kc = 0; kc < 5; kc++) {
            const int ko = kc * 16;
            uint32_t ah[4], al[4];
            ldsm_x4(ah, uQh + (uint32_t)(((wm + a_r) * QP + ko + a_c) * 2));
            ldsm_x4(al, uQl + (uint32_t)(((wm + a_r) * QP + ko + a_c) * 2));
#pragma unroll
            for (int p = 0; p < 4; p++) {
                const uint32_t off = (uint32_t)(((p * 16 + b_r) * QP + ko + b_c) * 2);
                uint32_t rh[4], rl[4];
                ldsm_x4(rh, uKh + off);
                ldsm_x4(rl, uKl + off);
                mma16816(sacc[2 * p],     ah, rh);
                mma16816(sacc[2 * p],     ah, rl);
                mma16816(sacc[2 * p],     al, rh);
                mma16816(sacc[2 * p + 1], ah, rh + 2);
                mma16816(sacc[2 * p + 1], ah, rl + 2);
                mma16816(sacc[2 * p + 1], al, rh + 2);
            }
        }

        // scale + causal mask (additive -10000, matches reference)
        const bool edge = (kb >= 2 * qt);
#pragma unroll
        for (int ni = 0; ni < 8; ni++) {
#pragma unroll
            for (int q = 0; q < 4; q++) {
                float v = sacc[ni][q] * scale;
                if (edge) {
                    const int key = kb * 64 + ni * 8 + t4 * 2 + (q & 1);
                    const int qr  = (q < 2) ? gr0 : gr1;
                    if (key > qr) v -= 10000.f;
                }
                sacc[ni][q] = v;
            }
        }

        // online softmax
        float mx0 = -1e30f, mx1 = -1e30f;
#pragma unroll
        for (int ni = 0; ni < 8; ni++) {
            mx0 = fmaxf(mx0, fmaxf(sacc[ni][0], sacc[ni][1]));
            mx1 = fmaxf(mx1, fmaxf(sacc[ni][2], sacc[ni][3]));
        }
        mx0 = fmaxf(mx0, __shfl_xor_sync(0xffffffffu, mx0, 1));
        mx0 = fmaxf(mx0, __shfl_xor_sync(0xffffffffu, mx0, 2));
        mx1 = fmaxf(mx1, __shfl_xor_sync(0xffffffffu, mx1, 1));
        mx1 = fmaxf(mx1, __shfl_xor_sync(0xffffffffu, mx1, 2));
        const float mn0 = fmaxf(m0, mx0), mn1 = fmaxf(m1, mx1);
        const float c0 = __expf(m0 - mn0), c1 = __expf(m1 - mn1);
        float s0 = 0.f, s1 = 0.f;
#pragma unroll
        for (int ni = 0; ni < 8; ni++) {
            sacc[ni][0] = __expf(sacc[ni][0] - mn0);
            sacc[ni][1] = __expf(sacc[ni][1] - mn0);
            sacc[ni][2] = __expf(sacc[ni][2] - mn1);
            sacc[ni][3] = __expf(sacc[ni][3] - mn1);
            s0 += sacc[ni][0] + sacc[ni][1];
            s1 += sacc[ni][2] + sacc[ni][3];
        }
        s0 += __shfl_xor_sync(0xffffffffu, s0, 1);
        s0 += __shfl_xor_sync(0xffffffffu, s0, 2);
        s1 += __shfl_xor_sync(0xffffffffu, s1, 1);
        s1 += __shfl_xor_sync(0xffffffffu, s1, 2);
        l0 = l0 * c0 + s0;  m0 = mn0;
        l1 = l1 * c1 + s1;  m1 = mn1;

#pragma unroll
        for (int nj = 0; nj < 10; nj++) {
            oacc[nj][0] *= c0; oacc[nj][1] *= c0;
            oacc[nj][2] *= c1; oacc[nj][3] *= c1;
        }

        // O += P @ V  (P in regs; V^T fragments via ldmatrix.trans)
#pragma unroll
        for (int kc2 = 0; kc2 < 4; kc2++) {
            uint32_t aph[4], apl[4];
            split_pack2(sacc[2 * kc2][0],     sacc[2 * kc2][1],     aph[0], apl[0]);
            split_pack2(sacc[2 * kc2][2],     sacc[2 * kc2][3],     aph[1], apl[1]);
            split_pack2(sacc[2 * kc2 + 1][0], sacc[2 * kc2 + 1][1], aph[2], apl[2]);
            split_pack2(sacc[2 * kc2 + 1][2], sacc[2 * kc2 + 1][3], aph[3], apl[3]);
            const int ko2 = kc2 * 16;
#pragma unroll
            for (int p = 0; p < 5; p++) {
                const uint32_t off = (uint32_t)(((ko2 + v_r) * QP + p * 16 + v_c) * 2);
                uint32_t rh[4], rl[4];
                ldsm_x4_t(rh, uVh + off);
                ldsm_x4_t(rl, uVl + off);
                mma16816(oacc[2 * p],     aph, rh);
                mma16816(oacc[2 * p],     aph, rl);
                mma16816(oacc[2 * p],     apl, rh);
                mma16816(oacc[2 * p + 1], aph, rh + 2);
                mma16816(oacc[2 * p + 1], aph, rl + 2);
                mma16816(oacc[2 * p + 1], apl, rh + 2);
            }
        }
    }

    // Normalize and write ctx as bf16 hi/lo split (row-major [MROWS, DD])
    const float inv0 = 1.f / l0, inv1 = 1.f / l1;
    const size_t r0idx = ((size_t)b * SS + qbase + wm + g) * DD + h * DP;
    const size_t r1idx = r0idx + 8 * DD;
#pragma unroll
    for (int nj = 0; nj < 10; nj++) {
        const int col = nj * 8 + t4 * 2;
        uint32_t h0, l0p, h1, l1p;
        split_pack2(oacc[nj][0] * inv0, oacc[nj][1] * inv0, h0, l0p);
        split_pack2(oacc[nj][2] * inv1, oacc[nj][3] * inv1, h1, l1p);
        *(uint32_t*)&g_Chi[r0idx + col] = h0;
        *(uint32_t*)&g_Clo[r0idx + col] = l0p;
        *(uint32_t*)&g_Chi[r1idx + col] = h1;
        *(uint32_t*)&g_Clo[r1idx + col] = l1p;
    }
}

// ---------------------------------------------------------------------------
extern "C" void kernel_launch(void* const* d_in, const int* in_sizes, int n_in,
                              void* d_out, int out_size)
{
    const float* x  = (const float*)d_in[0];
    const float* Wq = (const float*)d_in[2];
    const float* bq = (const float*)d_in[3];
    const float* Wk = (const float*)d_in[4];
    const float* bk = (const float*)d_in[5];
    const float* Wv = (const float*)d_in[6];
    const float* bv = (const float*)d_in[7];
    const float* Wo = (const float*)d_in[8];
    const float* bo = (const float*)d_in[9];
    float* out = (float*)d_out;

    __nv_bfloat16 *xhi, *xlo, *wthi, *wtlo, *chi, *clo;
    cudaGetSymbolAddress((void**)&xhi, g_Xhi);
    cudaGetSymbolAddress((void**)&xlo, g_Xlo);
    cudaGetSymbolAddress((void**)&wthi, g_WThi);
    cudaGetSymbolAddress((void**)&wtlo, g_WTlo);
    cudaGetSymbolAddress((void**)&chi, g_Chi);
    cudaGetSymbolAddress((void**)&clo, g_Clo);

    // 1. split x
    {
        const int n2 = MROWS * DD / 2;
        split_kernel<<<(n2 + 255) / 256, 256>>>(x, xhi, xlo, n2);
    }
    // 2. transpose+split weights
    wsplit_kernel<<<dim3(40, 40), dim3(32, 8)>>>(Wq, 0);
    wsplit_kernel<<<dim3(40, 40), dim3(32, 8)>>>(Wk, DD);
    wsplit_kernel<<<dim3(40, 40), dim3(32, 8)>>>(Wv, 2 * DD);
    wsplit_kernel<<<dim3(40, 40), dim3(32, 8)>>>(Wo, 3 * DD);

    // 3. QKV projection (HMMA + ldmatrix + cp.async pipeline)
    cudaFuncSetAttribute(mma_gemm_kernel, cudaFuncAttributeMaxDynamicSharedMemorySize, GEMM_SMEM_BYTES);
    mma_gemm_kernel<<<dim3(NQKV / 128, MROWS / 128), 256, GEMM_SMEM_BYTES>>>(
        xhi, xlo, wthi, wtlo, bq, bk, bv, 0, nullptr);

    // 4. attention (HMMA flash + ldmatrix + cp.async)
    {
        const int smem_bytes = ATT_SMEM_BF16 * (int)sizeof(__nv_bfloat16);
        cudaFuncSetAttribute(attn_mma_kernel, cudaFuncAttributeMaxDynamicSharedMemorySize, smem_bytes);
        attn_mma_kernel<<<dim3(SS / 128, HH, BB), 256, smem_bytes>>>();
    }

    // 5. output projection (HMMA + ldmatrix + cp.async pipeline)
    mma_gemm_kernel<<<dim3(DD / 128, MROWS / 128), 256, GEMM_SMEM_BYTES>>>(
        chi, clo, wthi + (size_t)3 * DD * DD, wtlo + (size_t)3 * DD * DD,
        bo, nullptr, nullptr, 1, out);
}

// round 9
// speedup vs baseline: 2.9045x; 1.1196x over previous
#include <cuda_runtime.h>
#include <cuda_bf16.h>
#include <cstdint>
#include <math.h>

// Problem constants
#define BB 2
#define SS 2048
#define DD 1280
#define HH 16
#define DP 80
#define MROWS (BB * SS)          // 4096
#define NQKV (3 * DD)            // 3840

// ---------------------------------------------------------------------------
// Device scratch (allocation-free rule)
// ---------------------------------------------------------------------------
__device__ __nv_bfloat16 g_Qhi[BB * HH * SS * DP];
__device__ __nv_bfloat16 g_Qlo[BB * HH * SS * DP];
__device__ __nv_bfloat16 g_Khi[BB * HH * SS * DP];
__device__ __nv_bfloat16 g_Klo[BB * HH * SS * DP];
__device__ __nv_bfloat16 g_Vhi[BB * HH * SS * DP];
__device__ __nv_bfloat16 g_Vlo[BB * HH * SS * DP];

__device__ __nv_bfloat16 g_Xhi[MROWS * DD];
__device__ __nv_bfloat16 g_Xlo[MROWS * DD];
__device__ __nv_bfloat16 g_WThi[4 * DD * DD];   // rows [0,3840)=Wq,Wk,Wv^T ; [3840,5120)=Wo^T
__device__ __nv_bfloat16 g_WTlo[4 * DD * DD];
__device__ __nv_bfloat16 g_Chi[MROWS * DD];
__device__ __nv_bfloat16 g_Clo[MROWS * DD];

// ---------------------------------------------------------------------------
// mma.sync + ldmatrix + cp.async helpers (portable to sm_103)
// ---------------------------------------------------------------------------
__device__ __forceinline__ void mma16816(float* c, const uint32_t* a, const uint32_t* b) {
    asm volatile(
        "mma.sync.aligned.m16n8k16.row.col.f32.bf16.bf16.f32 "
        "{%0,%1,%2,%3}, {%4,%5,%6,%7}, {%8,%9}, {%0,%1,%2,%3};"
        : "+f"(c[0]), "+f"(c[1]), "+f"(c[2]), "+f"(c[3])
        : "r"(a[0]), "r"(a[1]), "r"(a[2]), "r"(a[3]), "r"(b[0]), "r"(b[1]));
}

__device__ __forceinline__ void ldsm_x4(uint32_t* r, uint32_t addr) {
    asm volatile("ldmatrix.sync.aligned.m8n8.x4.shared.b16 {%0,%1,%2,%3}, [%4];"
        : "=r"(r[0]), "=r"(r[1]), "=r"(r[2]), "=r"(r[3]) : "r"(addr));
}
__device__ __forceinline__ void ldsm_x4_t(uint32_t* r, uint32_t addr) {
    asm volatile("ldmatrix.sync.aligned.m8n8.x4.trans.shared.b16 {%0,%1,%2,%3}, [%4];"
        : "=r"(r[0]), "=r"(r[1]), "=r"(r[2]), "=r"(r[3]) : "r"(addr));
}

__device__ __forceinline__ uint32_t smem_u32(const void* p) {
    return (uint32_t)__cvta_generic_to_shared(p);
}

__device__ __forceinline__ void cp_async16(uint32_t dst, const void* src) {
    asm volatile("cp.async.ca.shared.global [%0], [%1], 16;" :: "r"(dst), "l"(src));
}
__device__ __forceinline__ void cp_commit() {
    asm volatile("cp.async.commit_group;");
}

// split a,b -> packed bf16x2 hi and lo
__device__ __forceinline__ void split_pack2(float a, float b, uint32_t& hi, uint32_t& lo) {
    __nv_bfloat16 ha = __float2bfloat16(a), hb = __float2bfloat16(b);
    __nv_bfloat16 la = __float2bfloat16(a - __bfloat162float(ha));
    __nv_bfloat16 lb = __float2bfloat16(b - __bfloat162float(hb));
    __nv_bfloat162 H = __nv_bfloat162(ha, hb);
    __nv_bfloat162 L = __nv_bfloat162(la, lb);
    hi = *(uint32_t*)&H;
    lo = *(uint32_t*)&L;
}

// ---------------------------------------------------------------------------
// fp32 -> (bf16 hi, bf16 lo) elementwise split
// ---------------------------------------------------------------------------
__global__ __launch_bounds__(256) void split_kernel(const float* __restrict__ src,
                                                    __nv_bfloat16* __restrict__ hi,
                                                    __nv_bfloat16* __restrict__ lo,
                                                    int n2) {
    int i = blockIdx.x * blockDim.x + threadIdx.x;
    if (i >= n2) return;
    float2 v = *(const float2*)(src + 2 * (size_t)i);
    __nv_bfloat16 h0 = __float2bfloat16(v.x);
    __nv_bfloat16 h1 = __float2bfloat16(v.y);
    __nv_bfloat16 l0 = __float2bfloat16(v.x - __bfloat162float(h0));
    __nv_bfloat16 l1 = __float2bfloat16(v.y - __bfloat162float(h1));
    *(__nv_bfloat162*)(hi + 2 * (size_t)i) = __nv_bfloat162(h0, h1);
    *(__nv_bfloat162*)(lo + 2 * (size_t)i) = __nv_bfloat162(l0, l1);
}

// ---------------------------------------------------------------------------
// W [K=1280, N=1280] row-major -> W^T split; blockIdx.z selects matrix
// ---------------------------------------------------------------------------
__global__ __launch_bounds__(256) void wsplit4_kernel(const float* __restrict__ W0,
                                                      const float* __restrict__ W1,
                                                      const float* __restrict__ W2,
                                                      const float* __restrict__ W3) {
    __shared__ float tile[32][33];
    const int z  = blockIdx.z;
    const float* W = (z == 0) ? W0 : (z == 1) ? W1 : (z == 2) ? W2 : W3;
    const int ro = z * DD;
    const int tx = threadIdx.x;
    const int ty = threadIdx.y;
    const int n0 = blockIdx.x * 32;
    const int k0 = blockIdx.y * 32;
#pragma unroll
    for (int q = 0; q < 4; q++)
        tile[ty + q * 8][tx] = W[(size_t)(k0 + ty + q * 8) * DD + n0 + tx];
    __syncthreads();
#pragma unroll
    for (int q = 0; q < 4; q++) {
        const int nn = n0 + ty + q * 8;
        const int kk = k0 + tx;
        float v = tile[tx][ty + q * 8];
        __nv_bfloat16 h = __float2bfloat16(v);
        __nv_bfloat16 l = __float2bfloat16(v - __bfloat162float(h));
        g_WThi[(size_t)(ro + nn) * DD + kk] = h;
        g_WTlo[(size_t)(ro + nn) * DD + kk] = l;
    }
}

// ---------------------------------------------------------------------------
// HMMA split-bf16 GEMM: ldmatrix feeds + cp.async 2-stage pipeline
// ---------------------------------------------------------------------------
#define BK2 32
#define AP 40                       // smem pitch in bf16 (80B rows)
#define GSTR (128 * AP)             // bf16 per array per stage
#define GEMM_SMEM_BYTES (2 * 4 * GSTR * 2)   // 2 stages x 4 arrays

__global__ __launch_bounds__(256, 2) void mma_gemm_kernel(
    const __nv_bfloat16* __restrict__ Ahi, const __nv_bfloat16* __restrict__ Alo,
    const __nv_bfloat16* __restrict__ Bhi, const __nv_bfloat16* __restrict__ Blo,
    const float* __restrict__ b0, const float* __restrict__ b1, const float* __restrict__ b2,
    int mode, float* __restrict__ outp)
{
    extern __shared__ __nv_bfloat16 dsm[];

    const int t    = threadIdx.x;
    const int wid  = t >> 5;
    const int lane = t & 31;
    const int n0   = blockIdx.x * 128;
    const int m0   = blockIdx.y * 128;
    const int wm   = (wid >> 2) * 64;
    const int wn   = (wid & 3) * 32;
    const int g    = lane >> 2;
    const int t4   = lane & 3;

    const int a_r = (lane & 7) + ((lane >> 3) & 1) * 8;
    const int a_c = (lane >> 4) * 8;
    const int b_r = (lane & 7) + ((lane >> 4) & 1) * 8;
    const int b_c = ((lane >> 3) & 1) * 8;

    const uint32_t sbase = smem_u32(dsm);

    const int lr = t >> 1;
    const int lc = (t & 1) * 16;

    const __nv_bfloat16* rowA_hi = Ahi + (size_t)(m0 + lr) * DD + lc;
    const __nv_bfloat16* rowA_lo = Alo + (size_t)(m0 + lr) * DD + lc;
    const __nv_bfloat16* rowB_hi = Bhi + (size_t)(n0 + lr) * DD + lc;
    const __nv_bfloat16* rowB_lo = Blo + (size_t)(n0 + lr) * DD + lc;
    const uint32_t dst_off = (uint32_t)((lr * AP + lc) * 2);

    float acc[4][4][4];
#pragma unroll
    for (int mi = 0; mi < 4; mi++)
#pragma unroll
        for (int ni = 0; ni < 4; ni++)
#pragma unroll
            for (int q = 0; q < 4; q++) acc[mi][ni][q] = 0.f;

    const int KCH = DD / BK2;       // 40

    {
        const uint32_t sb = sbase + dst_off;
        cp_async16(sb + 0 * GSTR * 2,      rowA_hi);
        cp_async16(sb + 0 * GSTR * 2 + 16, rowA_hi + 8);
        cp_async16(sb + 1 * GSTR * 2,      rowA_lo);
        cp_async16(sb + 1 * GSTR * 2 + 16, rowA_lo + 8);
        cp_async16(sb + 2 * GSTR * 2,      rowB_hi);
        cp_async16(sb + 2 * GSTR * 2 + 16, rowB_hi + 8);
        cp_async16(sb + 3 * GSTR * 2,      rowB_lo);
        cp_async16(sb + 3 * GSTR * 2 + 16, rowB_lo + 8);
        cp_commit();
    }

    for (int kc = 0; kc < KCH; kc++) {
        if (kc + 1 < KCH) {
            const int kk = (kc + 1) * BK2;
            const uint32_t sb = sbase + (uint32_t)(((kc + 1) & 1) * 4 * GSTR * 2) + dst_off;
            cp_async16(sb + 0 * GSTR * 2,      rowA_hi + kk);
            cp_async16(sb + 0 * GSTR * 2 + 16, rowA_hi + kk + 8);
            cp_async16(sb + 1 * GSTR * 2,      rowA_lo + kk);
            cp_async16(sb + 1 * GSTR * 2 + 16, rowA_lo + kk + 8);
            cp_async16(sb + 2 * GSTR * 2,      rowB_hi + kk);
            cp_async16(sb + 2 * GSTR * 2 + 16, rowB_hi + kk + 8);
            cp_async16(sb + 3 * GSTR * 2,      rowB_lo + kk);
            cp_async16(sb + 3 * GSTR * 2 + 16, rowB_lo + kk + 8);
            cp_commit();
            asm volatile("cp.async.wait_group 1;");
        } else {
            asm volatile("cp.async.wait_group 0;");
        }
        __syncthreads();

        const uint32_t st = sbase + (uint32_t)((kc & 1) * 4 * GSTR * 2);
        const uint32_t uAhi = st;
        const uint32_t uAlo = st + 1 * GSTR * 2;
        const uint32_t uBhi = st + 2 * GSTR * 2;
        const uint32_t uBlo = st + 3 * GSTR * 2;

#pragma unroll
        for (int ks = 0; ks < 2; ks++) {
            const int kb = ks * 16;
            uint32_t bh[4][2], bl[4][2];
#pragma unroll
            for (int p = 0; p < 2; p++) {
                const uint32_t off = (uint32_t)(((wn + p * 16 + b_r) * AP + kb + b_c) * 2);
                uint32_t r4[4];
                ldsm_x4(r4, uBhi + off);
                bh[2 * p][0] = r4[0]; bh[2 * p][1] = r4[1];
                bh[2 * p + 1][0] = r4[2]; bh[2 * p + 1][1] = r4[3];
                ldsm_x4(r4, uBlo + off);
                bl[2 * p][0] = r4[0]; bl[2 * p][1] = r4[1];
                bl[2 * p + 1][0] = r4[2]; bl[2 * p + 1][1] = r4[3];
            }
#pragma unroll
            for (int mi = 0; mi < 4; mi++) {
                const uint32_t off = (uint32_t)(((wm + mi * 16 + a_r) * AP + kb + a_c) * 2);
                uint32_t ah[4], al[4];
                ldsm_x4(ah, uAhi + off);
                ldsm_x4(al, uAlo + off);
#pragma unroll
                for (int ni = 0; ni < 4; ni++) {
                    mma16816(acc[mi][ni], ah, bh[ni]);
                    mma16816(acc[mi][ni], ah, bl[ni]);
                    mma16816(acc[mi][ni], al, bh[ni]);
                }
            }
        }
        __syncthreads();
    }

    // Epilogue
#pragma unroll
    for (int mi = 0; mi < 4; mi++) {
        const int r0 = m0 + wm + mi * 16 + g;
#pragma unroll
        for (int ni = 0; ni < 4; ni++) {
            const int cg0 = n0 + wn + ni * 8 + t4 * 2;
#pragma unroll
            for (int q = 0; q < 4; q++) {
                const int row = r0 + (q >> 1) * 8;
                const int cg  = cg0 + (q & 1);
                const float v = acc[mi][ni][q];
                if (mode == 0) {
                    const int which = cg / DD;
                    const int cl    = cg - which * DD;
                    const int head  = cl / DP;
                    const int dd    = cl - head * DP;
                    const float val = v + (which == 0 ? b0 : which == 1 ? b1 : b2)[cl];
                    __nv_bfloat16* dh = (which == 0) ? g_Qhi : (which == 1) ? g_Khi : g_Vhi;
                    __nv_bfloat16* dl = (which == 0) ? g_Qlo : (which == 1) ? g_Klo : g_Vlo;
                    const int b_ = row >> 11;
                    const int s_ = row & 2047;
                    const size_t idx = (((size_t)b_ * HH + head) * SS + s_) * DP + dd;
                    __nv_bfloat16 hv = __float2bfloat16(val);
                    dh[idx] = hv;
                    dl[idx] = __float2bfloat16(val - __bfloat162float(hv));
                } else {
                    outp[(size_t)row * DD + cg] = v + b0[cg];
                }
            }
        }
    }
}

// ---------------------------------------------------------------------------
// HMMA flash attention: 256 q-rows/CTA, 512 threads (16 warps x 16 rows),
// 64-key tiles with 2-stage cp.async double-buffered K/V pipeline.
// ---------------------------------------------------------------------------
#define QP 88                       // smem pitch bf16 (176B rows)
#define QROWS 256
#define KVSTG (4 * 64 * QP)         // bf16 per K/V stage (Kh,Kl,Vh,Vl)
#define ATT_SMEM_BYTES ((2 * QROWS * QP + 2 * KVSTG) * 2)

__global__ __launch_bounds__(512, 1) void attn_mma_kernel()
{
    extern __shared__ __nv_bfloat16 sm[];
    __nv_bfloat16* sQh = sm;
    __nv_bfloat16* sQl = sm + QROWS * QP;

    const int t    = threadIdx.x;
    const int wid  = t >> 5;
    const int lane = t & 31;
    const int g    = lane >> 2;
    const int t4   = lane & 3;
    // global big-tiles-first schedule
    const int idx   = blockIdx.x;            // 0..255
    const int qt    = 7 - (idx >> 5);        // 8 q-tiles, big first
    const int hb    = idx & 31;
    const int h     = hb & 15;
    const int b     = hb >> 4;
    const size_t bh_off = ((size_t)b * HH + h) * SS * DP;
    const int qbase = qt * QROWS;
    const int wm    = wid * 16;
    const float scale = 0.11180339887498948f;   // 1/sqrt(80)

    // ldmatrix lane address components
    const int a_r = (lane & 7) + ((lane >> 3) & 1) * 8;
    const int a_c = (lane >> 4) * 8;
    const int b_r = (lane & 7) + ((lane >> 4) & 1) * 8;
    const int b_c = ((lane >> 3) & 1) * 8;
    const int v_r = (lane & 7) + ((lane >> 3) & 1) * 8;
    const int v_c = ((lane >> 4) & 1) * 8;

    const uint32_t uQh = smem_u32(sQh), uQl = smem_u32(sQl);
    const uint32_t uKV = smem_u32(sm + 2 * QROWS * QP);

    const int ktiles = 4 * qt + 4;

    // Prologue: Q tile (256x80 hi+lo) + K/V tile 0, one cp.async group
    {
        const size_t qbyte = (bh_off + (size_t)qbase * DP) * 2;
        const char* qh = (const char*)g_Qhi + qbyte;
        const char* ql = (const char*)g_Qlo + qbyte;
#pragma unroll
        for (int it = 0; it < 10; it++) {
            const int id2 = t + it * 512;          // 0..5119
            const int arr = id2 / 2560;
            const int rem = id2 - arr * 2560;
            const int row = rem / 10;
            const int c16 = rem - row * 10;
            cp_async16((arr ? uQl : uQh) + (uint32_t)(row * (QP * 2) + c16 * 16),
                       (arr ? ql : qh) + (size_t)row * (DP * 2) + c16 * 16);
        }
        const size_t kbyte = bh_off * 2;
        const char* srcs[4] = {
            (const char*)g_Khi + kbyte, (const char*)g_Klo + kbyte,
            (const char*)g_Vhi + kbyte, (const char*)g_Vlo + kbyte };
#pragma unroll
        for (int it = 0; it < 5; it++) {
            const int id2 = t + it * 512;          // 0..2559
            const int arr = id2 / 640;
            const int rem = id2 - arr * 640;
            const int row = rem / 10;
            const int c16 = rem - row * 10;
            cp_async16(uKV + (uint32_t)(arr * (64 * QP * 2) + row * (QP * 2) + c16 * 16),
                       srcs[arr] + (size_t)row * (DP * 2) + c16 * 16);
        }
        cp_commit();
    }

    float oacc[10][4];
#pragma unroll
    for (int nj = 0; nj < 10; nj++)
#pragma unroll
        for (int q = 0; q < 4; q++) oacc[nj][q] = 0.f;
    float m0 = -1e30f, m1 = -1e30f, l0 = 0.f, l1 = 0.f;

    const int gr0 = qbase + wm + g;
    const int gr1 = gr0 + 8;

    for (int kb = 0; kb < ktiles; kb++) {
        // prefetch next K/V tile into the other stage
        if (kb + 1 < ktiles) {
            const size_t kbyte = (bh_off + (size_t)(kb + 1) * 64 * DP) * 2;
            const char* srcs[4] = {
                (const char*)g_Khi + kbyte, (const char*)g_Klo + kbyte,
                (const char*)g_Vhi + kbyte, (const char*)g_Vlo + kbyte };
            const uint32_t dstb = uKV + (uint32_t)(((kb + 1) & 1) * KVSTG * 2);
#pragma unroll
            for (int it = 0; it < 5; it++) {
                const int id2 = t + it * 512;
                const int arr = id2 / 640;
                const int rem = id2 - arr * 640;
                const int row = rem / 10;
                const int c16 = rem - row * 10;
                cp_async16(dstb + (uint32_t)(arr * (64 * QP * 2) + row * (QP * 2) + c16 * 16),
                           srcs[arr] + (size_t)row * (DP * 2) + c16 * 16);
            }
            cp_commit();
            asm volatile("cp.async.wait_group 1;");
        } else {
            asm volatile("cp.async.wait_group 0;");
        }
        __syncthreads();

        const uint32_t stb = uKV + (uint32_t)((kb & 1) * KVSTG * 2);
        const uint32_t uKh = stb;
        const uint32_t uKl = stb + (uint32_t)(64 * QP * 2);
        const uint32_t uVh = stb + (uint32_t)(2 * 64 * QP * 2);
        const uint32_t uVl = stb + (uint32_t)(3 * 64 * QP * 2);

        // S = Q @ K^T
        float sacc[8][4];
#pragma unroll
        for (int ni = 0; ni < 8; ni++)
#pragma unroll
            for (int q = 0; q < 4; q++) sacc[ni][q] = 0.f;

#pragma unroll
        for (int kc = 0; kc < 5; kc++) {
            const int ko = kc * 16;
            uint32_t ah[4], al[4];
            ldsm_x4(ah, uQh + (uint32_t)(((wm + a_r) * QP + ko + a_c) * 2));
            ldsm_x4(al, uQl + (uint32_t)(((wm + a_r) * QP + ko + a_c) * 2));
#pragma unroll
            for (int p = 0; p < 4; p++) {
                const uint32_t off = (uint32_t)(((p * 16 + b_r) * QP + ko + b_c) * 2);
                uint32_t rh[4], rl[4];
                ldsm_x4(rh, uKh + off);
                ldsm_x4(rl, uKl + off);
                mma16816(sacc[2 * p],     ah, rh);
                mma16816(sacc[2 * p],     ah, rl);
                mma16816(sacc[2 * p],     al, rh);
                mma16816(sacc[2 * p + 1], ah, rh + 2);
                mma16816(sacc[2 * p + 1], ah, rl + 2);
                mma16816(sacc[2 * p + 1], al, rh + 2);
            }
        }

        // scale + causal mask (additive -10000, matches reference)
        const bool edge = (kb >= 4 * qt);
#pragma unroll
        for (int ni = 0; ni < 8; ni++) {
#pragma unroll
            for (int q = 0; q < 4; q++) {
                float v = sacc[ni][q] * scale;
                if (edge) {
                    const int key = kb * 64 + ni * 8 + t4 * 2 + (q & 1);
                    const int qr  = (q < 2) ? gr0 : gr1;
                    if (key > qr) v -= 10000.f;
                }
                sacc[ni][q] = v;
            }
        }

        // online softmax
        float mx0 = -1e30f, mx1 = -1e30f;
#pragma unroll
        for (int ni = 0; ni < 8; ni++) {
            mx0 = fmaxf(mx0, fmaxf(sacc[ni][0], sacc[ni][1]));
            mx1 = fmaxf(mx1, fmaxf(sacc[ni][2], sacc[ni][3]));
        }
        mx0 = fmaxf(mx0, __shfl_xor_sync(0xffffffffu, mx0, 1));
        mx0 = fmaxf(mx0, __shfl_xor_sync(0xffffffffu, mx0, 2));
        mx1 = fmaxf(mx1, __shfl_xor_sync(0xffffffffu, mx1, 1));
        mx1 = fmaxf(mx1, __shfl_xor_sync(0xffffffffu, mx1, 2));
        const float mn0 = fmaxf(m0, mx0), mn1 = fmaxf(m1, mx1);
        const float c0 = __expf(m0 - mn0), c1 = __expf(m1 - mn1);
        float s0 = 0.f, s1 = 0.f;
#pragma unroll
        for (int ni = 0; ni < 8; ni++) {
            sacc[ni][0] = __expf(sacc[ni][0] - mn0);
            sacc[ni][1] = __expf(sacc[ni][1] - mn0);
            sacc[ni][2] = __expf(sacc[ni][2] - mn1);
            sacc[ni][3] = __expf(sacc[ni][3] - mn1);
            s0 += sacc[ni][0] + sacc[ni][1];
            s1 += sacc[ni][2] + sacc[ni][3];
        }
        s0 += __shfl_xor_sync(0xffffffffu, s0, 1);
        s0 += __shfl_xor_sync(0xffffffffu, s0, 2);
        s1 += __shfl_xor_sync(0xffffffffu, s1, 1);
        s1 += __shfl_xor_sync(0xffffffffu, s1, 2);
        l0 = l0 * c0 + s0;  m0 = mn0;
        l1 = l1 * c1 + s1;  m1 = mn1;

#pragma unroll
        for (int nj = 0; nj < 10; nj++) {
            oacc[nj][0] *= c0; oacc[nj][1] *= c0;
            oacc[nj][2] *= c1; oacc[nj][3] *= c1;
        }

        // O += P @ V  (P in regs; V^T fragments via ldmatrix.trans)
#pragma unroll
        for (int kc2 = 0; kc2 < 4; kc2++) {
            uint32_t aph[4], apl[4];
            split_pack2(sacc[2 * kc2][0],     sacc[2 * kc2][1],     aph[0], apl[0]);
            split_pack2(sacc[2 * kc2][2],     sacc[2 * kc2][3],     aph[1], apl[1]);
            split_pack2(sacc[2 * kc2 + 1][0], sacc[2 * kc2 + 1][1], aph[2], apl[2]);
            split_pack2(sacc[2 * kc2 + 1][2], sacc[2 * kc2 + 1][3], aph[3], apl[3]);
            const int ko2 = kc2 * 16;
#pragma unroll
            for (int p = 0; p < 5; p++) {
                const uint32_t off = (uint32_t)(((ko2 + v_r) * QP + p * 16 + v_c) * 2);
                uint32_t rh[4], rl[4];
                ldsm_x4_t(rh, uVh + off);
                ldsm_x4_t(rl, uVl + off);
                mma16816(oacc[2 * p],     aph, rh);
                mma16816(oacc[2 * p],     aph, rl);
                mma16816(oacc[2 * p],     apl, rh);
                mma16816(oacc[2 * p + 1], aph, rh + 2);
                mma16816(oacc[2 * p + 1], aph, rl + 2);
                mma16816(oacc[2 * p + 1], apl, rh + 2);
            }
        }
        __syncthreads();
    }

    // Normalize and write ctx as bf16 hi/lo split (row-major [MROWS, DD])
    const float inv0 = 1.f / l0, inv1 = 1.f / l1;
    const size_t r0idx = ((size_t)b * SS + qbase + wm + g) * DD + h * DP;
    const size_t r1idx = r0idx + 8 * DD;
#pragma unroll
    for (int nj = 0; nj < 10; nj++) {
        const int col = nj * 8 + t4 * 2;
        uint32_t h0, l0p, h1, l1p;
        split_pack2(oacc[nj][0] * inv0, oacc[nj][1] * inv0, h0, l0p);
        split_pack2(oacc[nj][2] * inv1, oacc[nj][3] * inv1, h1, l1p);
        *(uint32_t*)&g_Chi[r0idx + col] = h0;
        *(uint32_t*)&g_Clo[r0idx + col] = l0p;
        *(uint32_t*)&g_Chi[r1idx + col] = h1;
        *(uint32_t*)&g_Clo[r1idx + col] = l1p;
    }
}

// ---------------------------------------------------------------------------
extern "C" void kernel_launch(void* const* d_in, const int* in_sizes, int n_in,
                              void* d_out, int out_size)
{
    const float* x  = (const float*)d_in[0];
    const float* Wq = (const float*)d_in[2];
    const float* bq = (const float*)d_in[3];
    const float* Wk = (const float*)d_in[4];
    const float* bk = (const float*)d_in[5];
    const float* Wv = (const float*)d_in[6];
    const float* bv = (const float*)d_in[7];
    const float* Wo = (const float*)d_in[8];
    const float* bo = (const float*)d_in[9];
    float* out = (float*)d_out;

    __nv_bfloat16 *xhi, *xlo, *wthi, *wtlo, *chi, *clo;
    cudaGetSymbolAddress((void**)&xhi, g_Xhi);
    cudaGetSymbolAddress((void**)&xlo, g_Xlo);
    cudaGetSymbolAddress((void**)&wthi, g_WThi);
    cudaGetSymbolAddress((void**)&wtlo, g_WTlo);
    cudaGetSymbolAddress((void**)&chi, g_Chi);
    cudaGetSymbolAddress((void**)&clo, g_Clo);

    // 1. split x
    {
        const int n2 = MROWS * DD / 2;
        split_kernel<<<(n2 + 255) / 256, 256>>>(x, xhi, xlo, n2);
    }
    // 2. transpose+split weights (one launch, z selects matrix)
    wsplit4_kernel<<<dim3(40, 40, 4), dim3(32, 8)>>>(Wq, Wk, Wv, Wo);

    // 3. QKV projection (HMMA + ldmatrix + cp.async pipeline)
    cudaFuncSetAttribute(mma_gemm_kernel, cudaFuncAttributeMaxDynamicSharedMemorySize, GEMM_SMEM_BYTES);
    mma_gemm_kernel<<<dim3(NQKV / 128, MROWS / 128), 256, GEMM_SMEM_BYTES>>>(
        xhi, xlo, wthi, wtlo, bq, bk, bv, 0, nullptr);

    // 4. attention (HMMA flash, double-buffered K/V pipeline)
    cudaFuncSetAttribute(attn_mma_kernel, cudaFuncAttributeMaxDynamicSharedMemorySize, ATT_SMEM_BYTES);
    attn_mma_kernel<<<256, 512, ATT_SMEM_BYTES>>>();

    // 5. output projection (HMMA + ldmatrix + cp.async pipeline)
    mma_gemm_kernel<<<dim3(DD / 128, MROWS / 128), 256, GEMM_SMEM_BYTES>>>(
        chi, clo, wthi + (size_t)3 * DD * DD, wtlo + (size_t)3 * DD * DD,
        bo, nullptr, nullptr, 1, out);
}